// round 3
// baseline (speedup 1.0000x reference)
#include <cuda_runtime.h>
#include <math.h>

// ---------------------------------------------------------------------------
// Problem constants
// ---------------------------------------------------------------------------
#define BATCH  8
#define NSEQ   4096
#define NTOK   (BATCH * NSEQ)   // 32768
#define DIM    512              // D = TOKEN_DIM * NUM_HEADS
#define TOKD   256
#define SCALEF 0.0625f          // 256^-0.5

// ---------------------------------------------------------------------------
// Device scratch (no allocations allowed)
// ---------------------------------------------------------------------------
__device__ __align__(256) float g_qbuf[(size_t)NTOK * DIM];   // 64 MB, q normalized in-place
__device__ __align__(256) float g_kbuf[(size_t)NTOK * DIM];   // 64 MB, k normalized in-place
__device__ __align__(256) float g_a[NTOK];                    // per-token alpha raw
__device__ __align__(256) float g_beta[NTOK];                 // per-token beta raw
__device__ __align__(256) float g_asumsq[BATCH];
__device__ __align__(256) float g_bsumsq[BATCH];
__device__ __align__(256) float g_gqraw[BATCH * DIM];
__device__ __align__(256) float g_gkraw[BATCH * DIM];
__device__ __align__(256) float g_gq[BATCH * DIM];
__device__ __align__(256) float g_gw[BATCH * DIM];            // g_q * w_beta
__device__ __align__(256) float g_gk[BATCH * DIM];

// ---------------------------------------------------------------------------
// Block reductions
// ---------------------------------------------------------------------------
__device__ __forceinline__ float block_sum(float v, float* sh) {
    #pragma unroll
    for (int o = 16; o > 0; o >>= 1) v += __shfl_xor_sync(0xffffffffu, v, o);
    int w = threadIdx.x >> 5;
    if ((threadIdx.x & 31) == 0) sh[w] = v;
    __syncthreads();
    int nw = blockDim.x >> 5;
    if (threadIdx.x < 32) {
        float s = (threadIdx.x < nw) ? sh[threadIdx.x] : 0.f;
        #pragma unroll
        for (int o = 16; o > 0; o >>= 1) s += __shfl_xor_sync(0xffffffffu, s, o);
        if (threadIdx.x == 0) sh[0] = s;
    }
    __syncthreads();
    float r = sh[0];
    __syncthreads();
    return r;
}

__device__ __forceinline__ float block_max(float v, float* sh) {
    #pragma unroll
    for (int o = 16; o > 0; o >>= 1) v = fmaxf(v, __shfl_xor_sync(0xffffffffu, v, o));
    int w = threadIdx.x >> 5;
    if ((threadIdx.x & 31) == 0) sh[w] = v;
    __syncthreads();
    int nw = blockDim.x >> 5;
    if (threadIdx.x < 32) {
        float s = (threadIdx.x < nw) ? sh[threadIdx.x] : -3.4e38f;
        #pragma unroll
        for (int o = 16; o > 0; o >>= 1) s = fmaxf(s, __shfl_xor_sync(0xffffffffu, s, o));
        if (threadIdx.x == 0) sh[0] = s;
    }
    __syncthreads();
    float r = sh[0];
    __syncthreads();
    return r;
}

// ---------------------------------------------------------------------------
// Zero the accumulators
// ---------------------------------------------------------------------------
__global__ void zero_scratch() {
    int i = blockIdx.x * blockDim.x + threadIdx.x;
    if (i < BATCH * DIM) { g_gqraw[i] = 0.f; g_gkraw[i] = 0.f; }
    if (i < BATCH)       { g_asumsq[i] = 0.f; g_bsumsq[i] = 0.f; }
}

// ---------------------------------------------------------------------------
// GEMM 1: C = x @ W + b,  M=32768, N=512, K=512.  DST=0 -> g_qbuf, 1 -> g_kbuf
// 128x128 block tile, BK=16, 256 threads, 8x8 per-thread register tile.
// ---------------------------------------------------------------------------
template <int DST>
__global__ __launch_bounds__(256) void gemm_qk(const float* __restrict__ A,
                                               const float* __restrict__ B,
                                               const float* __restrict__ bias) {
    constexpr int N = DIM, K = DIM;
    float* __restrict__ C = DST ? g_kbuf : g_qbuf;
    __shared__ __align__(16) float As[16][128];
    __shared__ __align__(16) float Bs[16][128];
    const int tid = threadIdx.x;
    const int tx = tid & 15, ty = tid >> 4;
    const int m0 = blockIdx.y * 128;
    const int n0 = blockIdx.x * 128;

    float acc[8][8];
    #pragma unroll
    for (int i = 0; i < 8; i++)
        #pragma unroll
        for (int j = 0; j < 8; j++) acc[i][j] = 0.f;

    for (int k0 = 0; k0 < K; k0 += 16) {
        #pragma unroll
        for (int l = 0; l < 2; l++) {
            int f = tid + l * 256;
            int row = f >> 2, c4 = f & 3;
            float4 v = *(const float4*)(A + (size_t)(m0 + row) * K + (k0 + c4 * 4));
            As[c4 * 4 + 0][row] = v.x;
            As[c4 * 4 + 1][row] = v.y;
            As[c4 * 4 + 2][row] = v.z;
            As[c4 * 4 + 3][row] = v.w;
        }
        #pragma unroll
        for (int l = 0; l < 2; l++) {
            int f = tid + l * 256;
            int row = f >> 5, c4 = f & 31;
            *(float4*)(&Bs[row][c4 * 4]) =
                *(const float4*)(B + (size_t)(k0 + row) * N + (n0 + c4 * 4));
        }
        __syncthreads();
        #pragma unroll
        for (int kk = 0; kk < 16; kk++) {
            float ra[8], rb[8];
            #pragma unroll
            for (int i = 0; i < 8; i++) ra[i] = As[kk][ty * 8 + i];
            #pragma unroll
            for (int j = 0; j < 8; j++) rb[j] = Bs[kk][tx * 8 + j];
            #pragma unroll
            for (int i = 0; i < 8; i++)
                #pragma unroll
                for (int j = 0; j < 8; j++) acc[i][j] = fmaf(ra[i], rb[j], acc[i][j]);
        }
        __syncthreads();
    }
    #pragma unroll
    for (int i = 0; i < 8; i++) {
        int m = m0 + ty * 8 + i;
        #pragma unroll
        for (int j = 0; j < 8; j += 4) {
            int n = n0 + tx * 8 + j;
            float4 o;
            o.x = acc[i][j + 0] + bias[n + 0];
            o.y = acc[i][j + 1] + bias[n + 1];
            o.z = acc[i][j + 2] + bias[n + 2];
            o.w = acc[i][j + 3] + bias[n + 3];
            *(float4*)(C + (size_t)m * N + n) = o;
        }
    }
}

// ---------------------------------------------------------------------------
// Normalize q,k rows in place; a[t] = SCALE * dot(q_hat, w_alpha);
// accumulate per-batch sum(a^2).   One block (128 thr) per token.
// ---------------------------------------------------------------------------
__global__ __launch_bounds__(128) void normalize_qk(const float* __restrict__ w_alpha) {
    const int t = blockIdx.x;
    const int b = t >> 12;          // / 4096
    const int tx = threadIdx.x;
    __shared__ float sh[32];
    float4* qp = reinterpret_cast<float4*>(g_qbuf) + (size_t)t * 128 + tx;
    float4* kp = reinterpret_cast<float4*>(g_kbuf) + (size_t)t * 128 + tx;
    float4 qv = *qp, kv = *kp;
    float sq = qv.x * qv.x + qv.y * qv.y + qv.z * qv.z + qv.w * qv.w;
    float sk = kv.x * kv.x + kv.y * kv.y + kv.z * kv.z + kv.w * kv.w;
    float tq = block_sum(sq, sh);
    float tk = block_sum(sk, sh);
    float qi = 1.f / fmaxf(sqrtf(tq), 1e-12f);
    float ki = 1.f / fmaxf(sqrtf(tk), 1e-12f);
    qv.x *= qi; qv.y *= qi; qv.z *= qi; qv.w *= qi;
    kv.x *= ki; kv.y *= ki; kv.z *= ki; kv.w *= ki;
    *qp = qv;
    *kp = kv;
    float4 wa = reinterpret_cast<const float4*>(w_alpha)[tx];
    float ad = qv.x * wa.x + qv.y * wa.y + qv.z * wa.z + qv.w * wa.w;
    float ta = block_sum(ad, sh);
    if (tx == 0) {
        float a = ta * SCALEF;
        g_a[t] = a;
        atomicAdd(&g_asumsq[b], a * a);
    }
}

// ---------------------------------------------------------------------------
// Weighted column sum: out[b,d] += sum_n w[b,n] * M[b,n,d]
// PASS 0: (g_a, g_qbuf)->g_gqraw    PASS 1: (g_beta, g_kbuf)->g_gkraw
// grid (32 n-chunks, 8 batches), 512 threads (one per d).
// ---------------------------------------------------------------------------
template <int PASS>
__global__ __launch_bounds__(512) void colsum() {
    const int b = blockIdx.y, chunk = blockIdx.x, d = threadIdx.x;
    const float* __restrict__ M = PASS ? g_kbuf : g_qbuf;
    const float* __restrict__ w = PASS ? g_beta : g_a;
    float* __restrict__ out = PASS ? g_gkraw : g_gqraw;
    const float* Mb = M + ((size_t)(b * NSEQ + chunk * 128)) * DIM + d;
    const float* wb = w + b * NSEQ + chunk * 128;
    float s = 0.f;
    #pragma unroll 4
    for (int n = 0; n < 128; n++) s = fmaf(wb[n], Mb[(size_t)n * DIM], s);
    atomicAdd(&out[b * DIM + d], s);
}

// ---------------------------------------------------------------------------
// g_q = softmax_d( g_gqraw / ||a_b|| ); also g_gw = g_q * w_beta.
// ---------------------------------------------------------------------------
__global__ __launch_bounds__(512) void gq_finalize(const float* __restrict__ w_beta) {
    const int b = blockIdx.x, d = threadIdx.x;
    __shared__ float sh[32];
    float inv = 1.f / fmaxf(sqrtf(g_asumsq[b]), 1e-12f);
    float v = g_gqraw[b * DIM + d] * inv;
    float mx = block_max(v, sh);
    float e = expf(v - mx);
    float s = block_sum(e, sh);
    float g = e / s;
    g_gq[b * DIM + d] = g;
    g_gw[b * DIM + d] = g * w_beta[d];
}

// ---------------------------------------------------------------------------
// beta[t] = SCALE * dot(k_hat[t,:], g_gw[b,:]);  accumulate sum(beta^2).
// ---------------------------------------------------------------------------
__global__ __launch_bounds__(128) void beta_kernel() {
    const int t = blockIdx.x;
    const int b = t >> 12;
    const int tx = threadIdx.x;
    __shared__ float sh[32];
    float4 kv = reinterpret_cast<const float4*>(g_kbuf)[(size_t)t * 128 + tx];
    float4 gw = reinterpret_cast<const float4*>(g_gw)[b * 128 + tx];
    float d = kv.x * gw.x + kv.y * gw.y + kv.z * gw.z + kv.w * gw.w;
    float td = block_sum(d, sh);
    if (tx == 0) {
        float bb = td * SCALEF;
        g_beta[t] = bb;
        atomicAdd(&g_bsumsq[b], bb * bb);
    }
}

// ---------------------------------------------------------------------------
// g_k = softmax_d( g_q * g_gkraw / ||beta_b|| )
// ---------------------------------------------------------------------------
__global__ __launch_bounds__(512) void gk_finalize() {
    const int b = blockIdx.x, d = threadIdx.x;
    __shared__ float sh[32];
    float inv = 1.f / fmaxf(sqrtf(g_bsumsq[b]), 1e-12f);
    float v = g_gq[b * DIM + d] * g_gkraw[b * DIM + d] * inv;
    float mx = block_max(v, sh);
    float e = expf(v - mx);
    float s = block_sum(e, sh);
    g_gk[b * DIM + d] = e / s;
}

// ---------------------------------------------------------------------------
// GEMM 2 (fused): out = (g_k * k_hat + q_hat) @ Wr + br
// M=32768, N=256, K=512. A-tile synthesized on load from g_kbuf/g_qbuf/g_gk.
// ---------------------------------------------------------------------------
__global__ __launch_bounds__(256) void gemm_final(const float* __restrict__ B,
                                                  const float* __restrict__ bias,
                                                  float* __restrict__ C) {
    constexpr int N = TOKD, K = DIM;
    __shared__ __align__(16) float As[16][128];
    __shared__ __align__(16) float Bs[16][128];
    const int tid = threadIdx.x;
    const int tx = tid & 15, ty = tid >> 4;
    const int m0 = blockIdx.y * 128;
    const int n0 = blockIdx.x * 128;

    float acc[8][8];
    #pragma unroll
    for (int i = 0; i < 8; i++)
        #pragma unroll
        for (int j = 0; j < 8; j++) acc[i][j] = 0.f;

    for (int k0 = 0; k0 < K; k0 += 16) {
        #pragma unroll
        for (int l = 0; l < 2; l++) {
            int f = tid + l * 256;
            int row = f >> 2, c4 = f & 3;
            int m = m0 + row;
            int bb = m >> 12;
            int kb = k0 + c4 * 4;
            float4 kv = *(const float4*)(g_kbuf + (size_t)m * DIM + kb);
            float4 qv = *(const float4*)(g_qbuf + (size_t)m * DIM + kb);
            float4 gk = *(const float4*)(g_gk + bb * DIM + kb);
            As[c4 * 4 + 0][row] = fmaf(gk.x, kv.x, qv.x);
            As[c4 * 4 + 1][row] = fmaf(gk.y, kv.y, qv.y);
            As[c4 * 4 + 2][row] = fmaf(gk.z, kv.z, qv.z);
            As[c4 * 4 + 3][row] = fmaf(gk.w, kv.w, qv.w);
        }
        #pragma unroll
        for (int l = 0; l < 2; l++) {
            int f = tid + l * 256;
            int row = f >> 5, c4 = f & 31;
            *(float4*)(&Bs[row][c4 * 4]) =
                *(const float4*)(B + (size_t)(k0 + row) * N + (n0 + c4 * 4));
        }
        __syncthreads();
        #pragma unroll
        for (int kk = 0; kk < 16; kk++) {
            float ra[8], rb[8];
            #pragma unroll
            for (int i = 0; i < 8; i++) ra[i] = As[kk][ty * 8 + i];
            #pragma unroll
            for (int j = 0; j < 8; j++) rb[j] = Bs[kk][tx * 8 + j];
            #pragma unroll
            for (int i = 0; i < 8; i++)
                #pragma unroll
                for (int j = 0; j < 8; j++) acc[i][j] = fmaf(ra[i], rb[j], acc[i][j]);
        }
        __syncthreads();
    }
    #pragma unroll
    for (int i = 0; i < 8; i++) {
        int m = m0 + ty * 8 + i;
        #pragma unroll
        for (int j = 0; j < 8; j += 4) {
            int n = n0 + tx * 8 + j;
            float4 o;
            o.x = acc[i][j + 0] + bias[n + 0];
            o.y = acc[i][j + 1] + bias[n + 1];
            o.z = acc[i][j + 2] + bias[n + 2];
            o.w = acc[i][j + 3] + bias[n + 3];
            *(float4*)(C + (size_t)m * N + n) = o;
        }
    }
}

// ---------------------------------------------------------------------------
// Launch
// ---------------------------------------------------------------------------
extern "C" void kernel_launch(void* const* d_in, const int* in_sizes, int n_in,
                              void* d_out, int out_size) {
    const float* x  = (const float*)d_in[0];
    const float* Wq = (const float*)d_in[1];
    const float* bq = (const float*)d_in[2];
    const float* Wk = (const float*)d_in[3];
    const float* bk = (const float*)d_in[4];
    const float* Wr = (const float*)d_in[5];
    const float* br = (const float*)d_in[6];
    const float* wa = (const float*)d_in[7];
    const float* wb = (const float*)d_in[8];
    float* out = (float*)d_out;

    zero_scratch<<<16, 256>>>();
    gemm_qk<0><<<dim3(4, 256), 256>>>(x, Wq, bq);
    gemm_qk<1><<<dim3(4, 256), 256>>>(x, Wk, bk);
    normalize_qk<<<NTOK, 128>>>(wa);
    colsum<0><<<dim3(32, BATCH), 512>>>();
    gq_finalize<<<BATCH, 512>>>(wb);
    beta_kernel<<<NTOK, 128>>>();
    colsum<1><<<dim3(32, BATCH), 512>>>();
    gk_finalize<<<BATCH, 512>>>();
    gemm_final<<<dim3(2, 256), 256>>>(Wr, br, out);
}

// round 7
// speedup vs baseline: 2.4208x; 2.4208x over previous
#include <cuda_runtime.h>
#include <math.h>
#include <stdint.h>

// ---------------------------------------------------------------------------
// Problem constants
// ---------------------------------------------------------------------------
#define BATCH  8
#define NSEQ   4096
#define NTOK   (BATCH * NSEQ)   // 32768
#define DIM    512
#define TOKD   256
#define SCALEF 0.0625f          // 256^-0.5

// ---------------------------------------------------------------------------
// Device scratch
// ---------------------------------------------------------------------------
__device__ __align__(256) float g_xr  [(size_t)NTOK * DIM];   // tf32-rounded x
__device__ __align__(256) float g_qbuf[(size_t)NTOK * DIM];   // RAW q (bias added, NOT normalized)
__device__ __align__(256) float g_kbuf[(size_t)NTOK * DIM];   // RAW k
__device__ __align__(256) float g_WqT[DIM * DIM];             // [n][k], tf32-rounded
__device__ __align__(256) float g_WkT[DIM * DIM];
__device__ __align__(256) float g_WrT[TOKD * DIM];
__device__ __align__(256) float g_ssq_q[NTOK];
__device__ __align__(256) float g_ssq_k[NTOK];
__device__ __align__(256) float g_adot [NTOK];
__device__ __align__(256) float g_qinv [NTOK];
__device__ __align__(256) float g_kinv [NTOK];
__device__ __align__(256) float g_wq   [NTOK];                // a[t] * qinv[t]
__device__ __align__(256) float g_wk   [NTOK];                // beta[t] * kinv[t]
__device__ __align__(256) float g_asumsq[BATCH];
__device__ __align__(256) float g_bsumsq[BATCH];
__device__ __align__(256) float g_gqraw[BATCH * DIM];
__device__ __align__(256) float g_gkraw[BATCH * DIM];
__device__ __align__(256) float g_gq[BATCH * DIM];
__device__ __align__(256) float g_gw[BATCH * DIM];
__device__ __align__(256) float g_gk[BATCH * DIM];

// ---------------------------------------------------------------------------
// PTX helpers
// ---------------------------------------------------------------------------
__device__ __forceinline__ uint32_t smem_u32(const void* p) {
    uint32_t a;
    asm("{ .reg .u64 t; cvta.to.shared.u64 t, %1; cvt.u32.u64 %0, t; }" : "=r"(a) : "l"(p));
    return a;
}
__device__ __forceinline__ uint32_t f2tf32(float f) {
    uint32_t u;
    asm("cvt.rna.tf32.f32 %0, %1;" : "=r"(u) : "f"(f));
    return u;
}
__device__ __forceinline__ void sts128(uint32_t a, uint32_t x, uint32_t y, uint32_t z, uint32_t w) {
    asm volatile("st.shared.v4.b32 [%0], {%1,%2,%3,%4};" :: "r"(a), "r"(x), "r"(y), "r"(z), "r"(w) : "memory");
}
__device__ __forceinline__ void cp16(uint32_t saddr, const void* g) {
    asm volatile("cp.async.cg.shared.global [%0], [%1], 16;" :: "r"(saddr), "l"(g) : "memory");
}
__device__ __forceinline__ void cp_commit() { asm volatile("cp.async.commit_group;" ::: "memory"); }
__device__ __forceinline__ void cp_wait0()  { asm volatile("cp.async.wait_group 0;" ::: "memory"); }
__device__ __forceinline__ void cp_wait1()  { asm volatile("cp.async.wait_group 1;" ::: "memory"); }

// mma.sync m16n8k8 tf32 (sm_80+ PTX — compiles for compute_103)
__device__ __forceinline__ void mma8(float* d, const uint32_t* a, const uint32_t* b) {
    asm volatile(
        "mma.sync.aligned.m16n8k8.row.col.f32.tf32.tf32.f32 "
        "{%0,%1,%2,%3}, {%4,%5,%6,%7}, {%8,%9}, {%0,%1,%2,%3};"
        : "+f"(d[0]), "+f"(d[1]), "+f"(d[2]), "+f"(d[3])
        : "r"(a[0]), "r"(a[1]), "r"(a[2]), "r"(a[3]), "r"(b[0]), "r"(b[1]));
}

// ---------------------------------------------------------------------------
// Block reductions
// ---------------------------------------------------------------------------
__device__ __forceinline__ float block_sum(float v, float* sh) {
    #pragma unroll
    for (int o = 16; o > 0; o >>= 1) v += __shfl_xor_sync(0xffffffffu, v, o);
    int w = threadIdx.x >> 5;
    if ((threadIdx.x & 31) == 0) sh[w] = v;
    __syncthreads();
    int nw = blockDim.x >> 5;
    if (threadIdx.x < 32) {
        float s = (threadIdx.x < nw) ? sh[threadIdx.x] : 0.f;
        #pragma unroll
        for (int o = 16; o > 0; o >>= 1) s += __shfl_xor_sync(0xffffffffu, s, o);
        if (threadIdx.x == 0) sh[0] = s;
    }
    __syncthreads();
    float r = sh[0];
    __syncthreads();
    return r;
}
__device__ __forceinline__ float block_max(float v, float* sh) {
    #pragma unroll
    for (int o = 16; o > 0; o >>= 1) v = fmaxf(v, __shfl_xor_sync(0xffffffffu, v, o));
    int w = threadIdx.x >> 5;
    if ((threadIdx.x & 31) == 0) sh[w] = v;
    __syncthreads();
    int nw = blockDim.x >> 5;
    if (threadIdx.x < 32) {
        float s = (threadIdx.x < nw) ? sh[threadIdx.x] : -3.4e38f;
        #pragma unroll
        for (int o = 16; o > 0; o >>= 1) s = fmaxf(s, __shfl_xor_sync(0xffffffffu, s, o));
        if (threadIdx.x == 0) sh[0] = s;
    }
    __syncthreads();
    float r = sh[0];
    __syncthreads();
    return r;
}

// ---------------------------------------------------------------------------
// zero accumulators
// ---------------------------------------------------------------------------
__global__ void zero_scratch() {
    int i = blockIdx.x * blockDim.x + threadIdx.x;
    if (i < NTOK) { g_ssq_q[i] = 0.f; g_ssq_k[i] = 0.f; g_adot[i] = 0.f; }
    if (i < BATCH * DIM) { g_gqraw[i] = 0.f; g_gkraw[i] = 0.f; }
    if (i < BATCH) { g_asumsq[i] = 0.f; g_bsumsq[i] = 0.f; }
}

// ---------------------------------------------------------------------------
// tf32-round x into g_xr
// ---------------------------------------------------------------------------
__global__ __launch_bounds__(256) void round_x(const float4* __restrict__ x) {
    const int n4 = NTOK * DIM / 4;
    for (int i = blockIdx.x * blockDim.x + threadIdx.x; i < n4; i += gridDim.x * blockDim.x) {
        float4 v = x[i];
        float4 o;
        o.x = __uint_as_float(f2tf32(v.x));
        o.y = __uint_as_float(f2tf32(v.y));
        o.z = __uint_as_float(f2tf32(v.z));
        o.w = __uint_as_float(f2tf32(v.w));
        reinterpret_cast<float4*>(g_xr)[i] = o;
    }
}

// ---------------------------------------------------------------------------
// Transpose weights [K,N] -> [N,K] with tf32 pre-rounding
// ---------------------------------------------------------------------------
__global__ void transpose_w(const float* __restrict__ Wq, const float* __restrict__ Wk,
                            const float* __restrict__ Wr) {
    __shared__ float t[32][33];
    int z = blockIdx.z;
    const float* src = (z == 0) ? Wq : (z == 1) ? Wk : Wr;
    float* dst = (z == 0) ? g_WqT : (z == 1) ? g_WkT : g_WrT;
    int ncols = (z == 2) ? TOKD : DIM;
    int k0 = blockIdx.y * 32, n0 = blockIdx.x * 32;
    if (n0 >= ncols) return;
    t[threadIdx.y][threadIdx.x] = src[(size_t)(k0 + threadIdx.y) * ncols + n0 + threadIdx.x];
    __syncthreads();
    dst[(size_t)(n0 + threadIdx.y) * DIM + k0 + threadIdx.x] =
        __uint_as_float(f2tf32(t[threadIdx.x][threadIdx.y]));
}

// ---------------------------------------------------------------------------
// Shared mma compute on a 128x128 tile step (BK=32), pad-36 smem rows
// warps: 2(M) x 4(N); warp tile 64x32
// ---------------------------------------------------------------------------
__device__ __forceinline__ void tile_compute(const float* __restrict__ As,
                                             const float* __restrict__ Bs,
                                             float acc[4][4][4],
                                             int warpM, int warpN, int g, int tg) {
    #pragma unroll
    for (int ks = 0; ks < 4; ks++) {
        uint32_t af[4][4], bf[4][2];
        #pragma unroll
        for (int mt = 0; mt < 4; mt++) {
            const float* p = As + (warpM * 64 + mt * 16 + g) * 36 + ks * 8 + tg;
            af[mt][0] = __float_as_uint(p[0]);
            af[mt][1] = __float_as_uint(p[8 * 36]);
            af[mt][2] = __float_as_uint(p[4]);
            af[mt][3] = __float_as_uint(p[8 * 36 + 4]);
        }
        #pragma unroll
        for (int nt = 0; nt < 4; nt++) {
            const float* p = Bs + (warpN * 32 + nt * 8 + g) * 36 + ks * 8 + tg;
            bf[nt][0] = __float_as_uint(p[0]);
            bf[nt][1] = __float_as_uint(p[4]);
        }
        #pragma unroll
        for (int mt = 0; mt < 4; mt++)
            #pragma unroll
            for (int nt = 0; nt < 4; nt++)
                mma8(acc[mt][nt], af[mt], bf[nt]);
    }
}

// ---------------------------------------------------------------------------
// GEMM q/k: Craw = xr @ W^T + bias. Epilogue accumulates per-row sum(v^2)
// (and v . w_alpha for ISQ) into global atomics. grid (4, 256), 256 threads.
// ---------------------------------------------------------------------------
#define SM_FLOATS 4608          // 128*36
#define GEMM_SMEM (4 * SM_FLOATS * 4)   // 73728 bytes

template <int ISQ>
__global__ void __launch_bounds__(256, 2)
mma_gemm_qk(const float* __restrict__ bias, const float* __restrict__ w_alpha) {
    const float* __restrict__ WT = ISQ ? g_WqT : g_WkT;
    float* __restrict__ C   = ISQ ? g_qbuf : g_kbuf;
    float* __restrict__ ssq = ISQ ? g_ssq_q : g_ssq_k;

    extern __shared__ float sm[];
    float* bufA[2] = { sm, sm + 2 * SM_FLOATS };
    float* bufB[2] = { sm + SM_FLOATS, sm + 3 * SM_FLOATS };
    __shared__ float sbias[DIM];
    __shared__ float swa[DIM];

    const int tid = threadIdx.x;
    const int lane = tid & 31, wid = tid >> 5;
    const int warpM = wid >> 2, warpN = wid & 3;
    const int g = lane >> 2, tg = lane & 3;
    const int m0 = blockIdx.y * 128, n0 = blockIdx.x * 128;
    const uint32_t sA[2] = { smem_u32(bufA[0]), smem_u32(bufA[1]) };
    const uint32_t sB[2] = { smem_u32(bufB[0]), smem_u32(bufB[1]) };

    for (int i = tid; i < DIM; i += 256) {
        sbias[i] = bias[i];
        if (ISQ) swa[i] = w_alpha[i];
    }

    float acc[4][4][4];
    #pragma unroll
    for (int a = 0; a < 4; a++)
        #pragma unroll
        for (int b = 0; b < 4; b++)
            #pragma unroll
            for (int c = 0; c < 4; c++) acc[a][b][c] = 0.f;

    auto load_tile = [&](int c, int buf) {
        const int k0 = c * 32;
        #pragma unroll
        for (int l = 0; l < 4; l++) {
            int e = tid + l * 256, r = e >> 3, s = e & 7;
            cp16(sA[buf] + (r * 36 + s * 4) * 4, g_xr + (size_t)(m0 + r) * DIM + k0 + s * 4);
        }
        #pragma unroll
        for (int l = 0; l < 4; l++) {
            int e = tid + l * 256, r = e >> 3, s = e & 7;
            cp16(sB[buf] + (r * 36 + s * 4) * 4, WT + (size_t)(n0 + r) * DIM + k0 + s * 4);
        }
        cp_commit();
    };

    load_tile(0, 0);
    #pragma unroll 1
    for (int c = 0; c < 16; c++) {
        if (c + 1 < 16) { load_tile(c + 1, (c + 1) & 1); cp_wait1(); }
        else cp_wait0();
        __syncthreads();
        tile_compute(bufA[c & 1], bufB[c & 1], acc, warpM, warpN, g, tg);
        __syncthreads();
    }

    // Epilogue: bias add, store raw C, row-wise ssq (+adot) partials
    #pragma unroll
    for (int mt = 0; mt < 4; mt++) {
        const int r1 = m0 + warpM * 64 + mt * 16 + g;
        const int r2 = r1 + 8;
        float s1 = 0.f, s2 = 0.f, a1 = 0.f, a2 = 0.f;
        #pragma unroll
        for (int nt = 0; nt < 4; nt++) {
            const int col = n0 + warpN * 32 + nt * 8 + 2 * tg;
            float v0 = acc[mt][nt][0] + sbias[col];
            float v1 = acc[mt][nt][1] + sbias[col + 1];
            float v2 = acc[mt][nt][2] + sbias[col];
            float v3 = acc[mt][nt][3] + sbias[col + 1];
            *(float2*)(C + (size_t)r1 * DIM + col) = make_float2(v0, v1);
            *(float2*)(C + (size_t)r2 * DIM + col) = make_float2(v2, v3);
            s1 = fmaf(v0, v0, fmaf(v1, v1, s1));
            s2 = fmaf(v2, v2, fmaf(v3, v3, s2));
            if (ISQ) {
                a1 = fmaf(v0, swa[col], fmaf(v1, swa[col + 1], a1));
                a2 = fmaf(v2, swa[col], fmaf(v3, swa[col + 1], a2));
            }
        }
        s1 += __shfl_xor_sync(0xffffffffu, s1, 1); s1 += __shfl_xor_sync(0xffffffffu, s1, 2);
        s2 += __shfl_xor_sync(0xffffffffu, s2, 1); s2 += __shfl_xor_sync(0xffffffffu, s2, 2);
        if (ISQ) {
            a1 += __shfl_xor_sync(0xffffffffu, a1, 1); a1 += __shfl_xor_sync(0xffffffffu, a1, 2);
            a2 += __shfl_xor_sync(0xffffffffu, a2, 1); a2 += __shfl_xor_sync(0xffffffffu, a2, 2);
        }
        if (tg == 0) {
            atomicAdd(&ssq[r1], s1);
            atomicAdd(&ssq[r2], s2);
            if (ISQ) { atomicAdd(&g_adot[r1], a1); atomicAdd(&g_adot[r2], a2); }
        }
    }
}

// ---------------------------------------------------------------------------
// Per-token finalize: inverse norms, alpha, wq weight, per-batch sum(a^2)
// ---------------------------------------------------------------------------
__global__ __launch_bounds__(256) void finalize_tok() {
    __shared__ float sh[32];
    const int t = blockIdx.x * 256 + threadIdx.x;
    const int b = t >> 12;
    float qi = 1.f / fmaxf(sqrtf(g_ssq_q[t]), 1e-12f);
    float ki = 1.f / fmaxf(sqrtf(g_ssq_k[t]), 1e-12f);
    g_qinv[t] = qi;
    g_kinv[t] = ki;
    float a = g_adot[t] * qi * SCALEF;
    g_wq[t] = a * qi;
    float s = block_sum(a * a, sh);
    if (threadIdx.x == 0) atomicAdd(&g_asumsq[b], s);
}

// ---------------------------------------------------------------------------
// Weighted column sums over RAW buffers (weight includes inv-norm)
// ---------------------------------------------------------------------------
template <int PASS>
__global__ __launch_bounds__(512) void colsum() {
    const int b = blockIdx.y, chunk = blockIdx.x, d = threadIdx.x;
    const float* __restrict__ M = PASS ? g_kbuf : g_qbuf;
    const float* __restrict__ w = PASS ? g_wk : g_wq;
    float* __restrict__ out = PASS ? g_gkraw : g_gqraw;
    const float* Mb = M + ((size_t)(b * NSEQ + chunk * 128)) * DIM + d;
    const float* wb = w + b * NSEQ + chunk * 128;
    float s = 0.f;
    #pragma unroll 4
    for (int n = 0; n < 128; n++) s = fmaf(wb[n], Mb[(size_t)n * DIM], s);
    atomicAdd(&out[b * DIM + d], s);
}

__global__ __launch_bounds__(512) void gq_finalize(const float* __restrict__ w_beta) {
    const int b = blockIdx.x, d = threadIdx.x;
    __shared__ float sh[32];
    float inv = 1.f / fmaxf(sqrtf(g_asumsq[b]), 1e-12f);
    float v = g_gqraw[b * DIM + d] * inv;
    float mx = block_max(v, sh);
    float e = expf(v - mx);
    float s = block_sum(e, sh);
    float gq = e / s;
    g_gq[b * DIM + d] = gq;
    g_gw[b * DIM + d] = gq * w_beta[d];
}

__global__ __launch_bounds__(128) void beta_kernel() {
    const int t = blockIdx.x;
    const int b = t >> 12;
    const int tx = threadIdx.x;
    __shared__ float sh[32];
    float4 kv = reinterpret_cast<const float4*>(g_kbuf)[(size_t)t * 128 + tx];
    float4 gw = reinterpret_cast<const float4*>(g_gw)[b * 128 + tx];
    float d = kv.x * gw.x + kv.y * gw.y + kv.z * gw.z + kv.w * gw.w;
    float td = block_sum(d, sh);
    if (tx == 0) {
        float ki = g_kinv[t];
        float bb = td * SCALEF * ki;          // beta on normalized k
        g_wk[t] = bb * ki;                    // weight applied to raw k
        atomicAdd(&g_bsumsq[b], bb * bb);
    }
}

__global__ __launch_bounds__(512) void gk_finalize() {
    const int b = blockIdx.x, d = threadIdx.x;
    __shared__ float sh[32];
    float inv = 1.f / fmaxf(sqrtf(g_bsumsq[b]), 1e-12f);
    float v = g_gq[b * DIM + d] * g_gkraw[b * DIM + d] * inv;
    float mx = block_max(v, sh);
    float e = expf(v - mx);
    float s = block_sum(e, sh);
    g_gk[b * DIM + d] = e / s;
}

// ---------------------------------------------------------------------------
// Final GEMM: out = (gk .* kinv .* kraw + qinv .* qraw) @ WrT^T + br
// grid (2, 256), 256 threads.
// ---------------------------------------------------------------------------
__global__ void __launch_bounds__(256)
mma_gemm_final(const float* __restrict__ bias, float* __restrict__ out) {
    extern __shared__ float sm[];
    float* bufA[2] = { sm, sm + 2 * SM_FLOATS };
    float* bufB[2] = { sm + SM_FLOATS, sm + 3 * SM_FLOATS };
    __shared__ float sbias[TOKD];
    __shared__ float sgk[DIM];
    __shared__ float sqinv[128];
    __shared__ float skinv[128];

    const int tid = threadIdx.x;
    const int lane = tid & 31, wid = tid >> 5;
    const int warpM = wid >> 2, warpN = wid & 3;
    const int g = lane >> 2, tg = lane & 3;
    const int m0 = blockIdx.y * 128, n0 = blockIdx.x * 128;
    const int b0 = m0 >> 12;
    const uint32_t sA[2] = { smem_u32(bufA[0]), smem_u32(bufA[1]) };
    const uint32_t sB[2] = { smem_u32(bufB[0]), smem_u32(bufB[1]) };

    for (int i = tid; i < TOKD; i += 256) sbias[i] = bias[i];
    for (int i = tid; i < DIM; i += 256) sgk[i] = g_gk[b0 * DIM + i];
    if (tid < 128) { sqinv[tid] = g_qinv[m0 + tid]; skinv[tid] = g_kinv[m0 + tid]; }

    float acc[4][4][4];
    #pragma unroll
    for (int a = 0; a < 4; a++)
        #pragma unroll
        for (int b = 0; b < 4; b++)
            #pragma unroll
            for (int c = 0; c < 4; c++) acc[a][b][c] = 0.f;

    auto load_B = [&](int c, int buf) {
        const int k0 = c * 32;
        #pragma unroll
        for (int l = 0; l < 4; l++) {
            int e = tid + l * 256, r = e >> 3, s = e & 7;
            cp16(sB[buf] + (r * 36 + s * 4) * 4, g_WrT + (size_t)(n0 + r) * DIM + k0 + s * 4);
        }
        cp_commit();
    };

    float4 kv[4], qv[4];
    auto fetch_A = [&](int c) {
        const int k0 = c * 32;
        #pragma unroll
        for (int l = 0; l < 4; l++) {
            int e = tid + l * 256, r = e >> 3, s = e & 7;
            kv[l] = *(const float4*)(g_kbuf + (size_t)(m0 + r) * DIM + k0 + s * 4);
            qv[l] = *(const float4*)(g_qbuf + (size_t)(m0 + r) * DIM + k0 + s * 4);
        }
    };
    auto sts_A = [&](int c, int buf) {
        const int k0 = c * 32;
        #pragma unroll
        for (int l = 0; l < 4; l++) {
            int e = tid + l * 256, r = e >> 3, s = e & 7;
            float qi = sqinv[r], ksc = skinv[r];
            int k = k0 + s * 4;
            float v0 = fmaf(sgk[k + 0] * ksc, kv[l].x, qi * qv[l].x);
            float v1 = fmaf(sgk[k + 1] * ksc, kv[l].y, qi * qv[l].y);
            float v2 = fmaf(sgk[k + 2] * ksc, kv[l].z, qi * qv[l].z);
            float v3 = fmaf(sgk[k + 3] * ksc, kv[l].w, qi * qv[l].w);
            sts128(sA[buf] + (r * 36 + s * 4) * 4,
                   f2tf32(v0), f2tf32(v1), f2tf32(v2), f2tf32(v3));
        }
    };

    fetch_A(0);
    load_B(0, 0);
    __syncthreads();                 // sqinv/sgk ready before first sts_A
    #pragma unroll 1
    for (int c = 0; c < 16; c++) {
        sts_A(c, c & 1);
        if (c + 1 < 16) { fetch_A(c + 1); load_B(c + 1, (c + 1) & 1); cp_wait1(); }
        else cp_wait0();
        __syncthreads();
        tile_compute(bufA[c & 1], bufB[c & 1], acc, warpM, warpN, g, tg);
        __syncthreads();
    }

    #pragma unroll
    for (int mt = 0; mt < 4; mt++) {
        const int r1 = m0 + warpM * 64 + mt * 16 + g;
        const int r2 = r1 + 8;
        #pragma unroll
        for (int nt = 0; nt < 4; nt++) {
            const int col = n0 + warpN * 32 + nt * 8 + 2 * tg;   // global out col
            float2 o1, o2;
            o1.x = acc[mt][nt][0] + sbias[col];
            o1.y = acc[mt][nt][1] + sbias[col + 1];
            o2.x = acc[mt][nt][2] + sbias[col];
            o2.y = acc[mt][nt][3] + sbias[col + 1];
            *(float2*)(out + (size_t)r1 * TOKD + col) = o1;
            *(float2*)(out + (size_t)r2 * TOKD + col) = o2;
        }
    }
}

// ---------------------------------------------------------------------------
// Launch
// ---------------------------------------------------------------------------
extern "C" void kernel_launch(void* const* d_in, const int* in_sizes, int n_in,
                              void* d_out, int out_size) {
    const float* x  = (const float*)d_in[0];
    const float* Wq = (const float*)d_in[1];
    const float* bq = (const float*)d_in[2];
    const float* Wk = (const float*)d_in[3];
    const float* bk = (const float*)d_in[4];
    const float* Wr = (const float*)d_in[5];
    const float* br = (const float*)d_in[6];
    const float* wa = (const float*)d_in[7];
    const float* wb = (const float*)d_in[8];
    float* out = (float*)d_out;

    cudaFuncSetAttribute(mma_gemm_qk<1>,  cudaFuncAttributeMaxDynamicSharedMemorySize, GEMM_SMEM);
    cudaFuncSetAttribute(mma_gemm_qk<0>,  cudaFuncAttributeMaxDynamicSharedMemorySize, GEMM_SMEM);
    cudaFuncSetAttribute(mma_gemm_final,  cudaFuncAttributeMaxDynamicSharedMemorySize, GEMM_SMEM);

    zero_scratch<<<128, 256>>>();
    round_x<<<2048, 256>>>((const float4*)x);
    transpose_w<<<dim3(16, 16, 3), dim3(32, 32)>>>(Wq, Wk, Wr);
    mma_gemm_qk<1><<<dim3(4, 256), 256, GEMM_SMEM>>>(bq, wa);
    mma_gemm_qk<0><<<dim3(4, 256), 256, GEMM_SMEM>>>(bk, wa);
    finalize_tok<<<128, 256>>>();
    colsum<0><<<dim3(32, BATCH), 512>>>();
    gq_finalize<<<BATCH, 512>>>(wb);
    beta_kernel<<<NTOK, 128>>>();
    colsum<1><<<dim3(32, BATCH), 512>>>();
    gk_finalize<<<BATCH, 512>>>();
    mma_gemm_final<<<dim3(2, 256), 256, GEMM_SMEM>>>(br, out);
}

// round 8
// speedup vs baseline: 3.1451x; 1.2992x over previous
#include <cuda_runtime.h>
#include <math.h>
#include <stdint.h>

// ---------------------------------------------------------------------------
// Problem constants
// ---------------------------------------------------------------------------
#define BATCH  8
#define NSEQ   4096
#define NTOK   (BATCH * NSEQ)   // 32768
#define DIM    512
#define TOKD   256
#define SCALEF 0.0625f          // 256^-0.5

// ---------------------------------------------------------------------------
// Device scratch
// ---------------------------------------------------------------------------
__device__ __align__(256) float g_qbuf[(size_t)NTOK * DIM];   // RAW q (bias added, NOT normalized)
__device__ __align__(256) float g_kbuf[(size_t)NTOK * DIM];   // RAW k
__device__ __align__(256) float g_WqT[DIM * DIM];             // [n][k], tf32-rounded
__device__ __align__(256) float g_WkT[DIM * DIM];
__device__ __align__(256) float g_WrT[TOKD * DIM];
__device__ __align__(256) float g_ssq_q[NTOK];
__device__ __align__(256) float g_ssq_k[NTOK];
__device__ __align__(256) float g_adot [NTOK];
__device__ __align__(256) float g_qinv [NTOK];
__device__ __align__(256) float g_kinv [NTOK];
__device__ __align__(256) float g_asumsq[BATCH];
__device__ __align__(256) float g_bsumsq[BATCH];
__device__ __align__(256) float g_gqraw[BATCH * DIM];
__device__ __align__(256) float g_gkraw[BATCH * DIM];
__device__ __align__(256) float g_gq[BATCH * DIM];
__device__ __align__(256) float g_gw[BATCH * DIM];
__device__ __align__(256) float g_gk[BATCH * DIM];

// ---------------------------------------------------------------------------
// PTX helpers
// ---------------------------------------------------------------------------
__device__ __forceinline__ uint32_t smem_u32(const void* p) {
    uint32_t a;
    asm("{ .reg .u64 t; cvta.to.shared.u64 t, %1; cvt.u32.u64 %0, t; }" : "=r"(a) : "l"(p));
    return a;
}
__device__ __forceinline__ uint32_t f2tf32(float f) {
    uint32_t u;
    asm("cvt.rna.tf32.f32 %0, %1;" : "=r"(u) : "f"(f));
    return u;
}
__device__ __forceinline__ void sts128(uint32_t a, uint32_t x, uint32_t y, uint32_t z, uint32_t w) {
    asm volatile("st.shared.v4.b32 [%0], {%1,%2,%3,%4};" :: "r"(a), "r"(x), "r"(y), "r"(z), "r"(w) : "memory");
}
__device__ __forceinline__ void cp16(uint32_t saddr, const void* g) {
    asm volatile("cp.async.cg.shared.global [%0], [%1], 16;" :: "r"(saddr), "l"(g) : "memory");
}
__device__ __forceinline__ void cp_commit() { asm volatile("cp.async.commit_group;" ::: "memory"); }
__device__ __forceinline__ void cp_wait0()  { asm volatile("cp.async.wait_group 0;" ::: "memory"); }
__device__ __forceinline__ void cp_wait1()  { asm volatile("cp.async.wait_group 1;" ::: "memory"); }

// mma.sync m16n8k8 tf32
__device__ __forceinline__ void mma8(float* d, const uint32_t* a, const uint32_t* b) {
    asm volatile(
        "mma.sync.aligned.m16n8k8.row.col.f32.tf32.tf32.f32 "
        "{%0,%1,%2,%3}, {%4,%5,%6,%7}, {%8,%9}, {%0,%1,%2,%3};"
        : "+f"(d[0]), "+f"(d[1]), "+f"(d[2]), "+f"(d[3])
        : "r"(a[0]), "r"(a[1]), "r"(a[2]), "r"(a[3]), "r"(b[0]), "r"(b[1]));
}
// ldmatrix x4: 4 8x8 b16 tiles == 4 8x4 fp32 tiles; lane -> (row i>>2, col i&3)
__device__ __forceinline__ void ldsm4(uint32_t* r, uint32_t addr) {
    asm volatile("ldmatrix.sync.aligned.m8n8.x4.shared.b16 {%0,%1,%2,%3}, [%4];"
        : "=r"(r[0]), "=r"(r[1]), "=r"(r[2]), "=r"(r[3]) : "r"(addr));
}

// ---------------------------------------------------------------------------
// Block reductions
// ---------------------------------------------------------------------------
__device__ __forceinline__ float block_sum(float v, float* sh) {
    #pragma unroll
    for (int o = 16; o > 0; o >>= 1) v += __shfl_xor_sync(0xffffffffu, v, o);
    int w = threadIdx.x >> 5;
    if ((threadIdx.x & 31) == 0) sh[w] = v;
    __syncthreads();
    int nw = blockDim.x >> 5;
    if (threadIdx.x < 32) {
        float s = (threadIdx.x < nw) ? sh[threadIdx.x] : 0.f;
        #pragma unroll
        for (int o = 16; o > 0; o >>= 1) s += __shfl_xor_sync(0xffffffffu, s, o);
        if (threadIdx.x == 0) sh[0] = s;
    }
    __syncthreads();
    float r = sh[0];
    __syncthreads();
    return r;
}
__device__ __forceinline__ float block_max(float v, float* sh) {
    #pragma unroll
    for (int o = 16; o > 0; o >>= 1) v = fmaxf(v, __shfl_xor_sync(0xffffffffu, v, o));
    int w = threadIdx.x >> 5;
    if ((threadIdx.x & 31) == 0) sh[w] = v;
    __syncthreads();
    int nw = blockDim.x >> 5;
    if (threadIdx.x < 32) {
        float s = (threadIdx.x < nw) ? sh[threadIdx.x] : -3.4e38f;
        #pragma unroll
        for (int o = 16; o > 0; o >>= 1) s = fmaxf(s, __shfl_xor_sync(0xffffffffu, s, o));
        if (threadIdx.x == 0) sh[0] = s;
    }
    __syncthreads();
    float r = sh[0];
    __syncthreads();
    return r;
}

// ---------------------------------------------------------------------------
// zero accumulators
// ---------------------------------------------------------------------------
__global__ void zero_scratch() {
    int i = blockIdx.x * blockDim.x + threadIdx.x;
    if (i < NTOK) { g_ssq_q[i] = 0.f; g_ssq_k[i] = 0.f; g_adot[i] = 0.f; }
    if (i < BATCH * DIM) { g_gqraw[i] = 0.f; g_gkraw[i] = 0.f; }
    if (i < BATCH) { g_asumsq[i] = 0.f; g_bsumsq[i] = 0.f; }
}

// ---------------------------------------------------------------------------
// Transpose weights [K,N] -> [N,K] with tf32 pre-rounding
// ---------------------------------------------------------------------------
__global__ void transpose_w(const float* __restrict__ Wq, const float* __restrict__ Wk,
                            const float* __restrict__ Wr) {
    __shared__ float t[32][33];
    int z = blockIdx.z;
    const float* src = (z == 0) ? Wq : (z == 1) ? Wk : Wr;
    float* dst = (z == 0) ? g_WqT : (z == 1) ? g_WkT : g_WrT;
    int ncols = (z == 2) ? TOKD : DIM;
    int k0 = blockIdx.y * 32, n0 = blockIdx.x * 32;
    if (n0 >= ncols) return;
    t[threadIdx.y][threadIdx.x] = src[(size_t)(k0 + threadIdx.y) * ncols + n0 + threadIdx.x];
    __syncthreads();
    dst[(size_t)(n0 + threadIdx.y) * DIM + k0 + threadIdx.x] =
        __uint_as_float(f2tf32(t[threadIdx.x][threadIdx.y]));
}

// ---------------------------------------------------------------------------
// ldmatrix-based tile compute: 4 warps (2x2), warp tile 64x64, BK=32,
// smem rows padded to 36 floats (conflict-free for LDSM & cp.async)
// ---------------------------------------------------------------------------
__device__ __forceinline__ void tile_compute_ldsm(uint32_t sAb, uint32_t sBb,
                                                  float acc[4][8][4],
                                                  int lane, int warpM, int warpN) {
    const int j = lane >> 3, i = lane & 7;
    const int arow = warpM * 64 + (j & 1) * 8 + i;
    const int acol = (j >> 1) * 4;
    const int brow = warpN * 64 + ((j >> 1) & 1) * 8 + i;
    const int bcol = (j & 1) * 4;
    #pragma unroll
    for (int ks = 0; ks < 4; ks++) {
        uint32_t af[4][4], bf[4][4];
        #pragma unroll
        for (int mt = 0; mt < 4; mt++)
            ldsm4(af[mt], sAb + ((arow + mt * 16) * 36 + ks * 8 + acol) * 4);
        #pragma unroll
        for (int ntp = 0; ntp < 4; ntp++)
            ldsm4(bf[ntp], sBb + ((brow + ntp * 16) * 36 + ks * 8 + bcol) * 4);
        #pragma unroll
        for (int mt = 0; mt < 4; mt++)
            #pragma unroll
            for (int nt = 0; nt < 8; nt++)
                mma8(acc[mt][nt], af[mt], &bf[nt >> 1][(nt & 1) * 2]);
    }
}

// ---------------------------------------------------------------------------
// Fused q+k GEMM: Craw = x @ W^T + bias (x truncated to tf32 by HW; bias-add
// in epilogue). Per-row ssq (+ adot for q) via shfl + global atomics.
// grid (8, 256): x<4 -> q n-tile, else k n-tile. 128 threads.
// ---------------------------------------------------------------------------
#define QK_SMF  4608                    // 128*36 floats per tile buffer
#define QK_SMEM (4 * QK_SMF * 4)        // 73728 bytes (A0,B0,A1,B1)

__global__ void __launch_bounds__(128, 2)
mma_gemm_qk2(const float* __restrict__ X,
             const float* __restrict__ bq, const float* __restrict__ bk,
             const float* __restrict__ w_alpha) {
    extern __shared__ float sm[];
    __shared__ float sbias[DIM];
    __shared__ float swa[DIM];

    const int isq = (blockIdx.x < 4);
    const int n0 = (blockIdx.x & 3) * 128;
    const int m0 = blockIdx.y * 128;
    const float* __restrict__ WT   = isq ? g_WqT : g_WkT;
    const float* __restrict__ bias = isq ? bq : bk;
    float* __restrict__ C   = isq ? g_qbuf : g_kbuf;
    float* __restrict__ ssq = isq ? g_ssq_q : g_ssq_k;

    const int tid = threadIdx.x, lane = tid & 31, wid = tid >> 5;
    const int warpM = wid >> 1, warpN = wid & 1;
    const uint32_t sA[2] = { smem_u32(sm),           smem_u32(sm + 2 * QK_SMF) };
    const uint32_t sB[2] = { smem_u32(sm + QK_SMF),  smem_u32(sm + 3 * QK_SMF) };

    for (int i = tid; i < DIM; i += 128) { sbias[i] = bias[i]; swa[i] = w_alpha[i]; }

    float acc[4][8][4];
    #pragma unroll
    for (int a = 0; a < 4; a++)
        #pragma unroll
        for (int b = 0; b < 8; b++)
            #pragma unroll
            for (int c = 0; c < 4; c++) acc[a][b][c] = 0.f;

    auto load_tile = [&](int c, int buf) {
        const int k0 = c * 32;
        #pragma unroll
        for (int l = 0; l < 8; l++) {
            int e = tid + l * 128, r = e >> 3, s = e & 7;
            cp16(sA[buf] + (r * 36 + s * 4) * 4, X + (size_t)(m0 + r) * DIM + k0 + s * 4);
        }
        #pragma unroll
        for (int l = 0; l < 8; l++) {
            int e = tid + l * 128, r = e >> 3, s = e & 7;
            cp16(sB[buf] + (r * 36 + s * 4) * 4, WT + (size_t)(n0 + r) * DIM + k0 + s * 4);
        }
        cp_commit();
    };

    load_tile(0, 0);
    #pragma unroll 1
    for (int c = 0; c < 16; c++) {
        if (c + 1 < 16) { load_tile(c + 1, (c + 1) & 1); cp_wait1(); }
        else cp_wait0();
        __syncthreads();
        tile_compute_ldsm(sA[c & 1], sB[c & 1], acc, lane, warpM, warpN);
        __syncthreads();
    }

    // Epilogue: bias, store raw C, per-row ssq (+adot)
    const int g = lane >> 2, tg = lane & 3;
    #pragma unroll
    for (int mt = 0; mt < 4; mt++) {
        const int r1 = m0 + warpM * 64 + mt * 16 + g;
        const int r2 = r1 + 8;
        float s1 = 0.f, s2 = 0.f, a1 = 0.f, a2 = 0.f;
        #pragma unroll
        for (int nt = 0; nt < 8; nt++) {
            const int col = n0 + warpN * 64 + nt * 8 + 2 * tg;
            float v0 = acc[mt][nt][0] + sbias[col];
            float v1 = acc[mt][nt][1] + sbias[col + 1];
            float v2 = acc[mt][nt][2] + sbias[col];
            float v3 = acc[mt][nt][3] + sbias[col + 1];
            *(float2*)(C + (size_t)r1 * DIM + col) = make_float2(v0, v1);
            *(float2*)(C + (size_t)r2 * DIM + col) = make_float2(v2, v3);
            s1 = fmaf(v0, v0, fmaf(v1, v1, s1));
            s2 = fmaf(v2, v2, fmaf(v3, v3, s2));
            if (isq) {
                a1 = fmaf(v0, swa[col], fmaf(v1, swa[col + 1], a1));
                a2 = fmaf(v2, swa[col], fmaf(v3, swa[col + 1], a2));
            }
        }
        s1 += __shfl_xor_sync(0xffffffffu, s1, 1); s1 += __shfl_xor_sync(0xffffffffu, s1, 2);
        s2 += __shfl_xor_sync(0xffffffffu, s2, 1); s2 += __shfl_xor_sync(0xffffffffu, s2, 2);
        if (isq) {
            a1 += __shfl_xor_sync(0xffffffffu, a1, 1); a1 += __shfl_xor_sync(0xffffffffu, a1, 2);
            a2 += __shfl_xor_sync(0xffffffffu, a2, 1); a2 += __shfl_xor_sync(0xffffffffu, a2, 2);
        }
        if (tg == 0) {
            atomicAdd(&ssq[r1], s1);
            atomicAdd(&ssq[r2], s2);
            if (isq) { atomicAdd(&g_adot[r1], a1); atomicAdd(&g_adot[r2], a2); }
        }
    }
}

// ---------------------------------------------------------------------------
// Fused finalize_tok + colsum0: per-token inv norms + alpha weight, then
// weighted column sum of RAW q into g_gqraw. grid (32, 8), 512 threads.
// ---------------------------------------------------------------------------
__global__ __launch_bounds__(512) void colsum0_fused() {
    __shared__ float sw[128];
    const int b = blockIdx.y, chunk = blockIdx.x;
    const int t0 = b * NSEQ + chunk * 128;
    const int tid = threadIdx.x;

    if (tid < 128) {
        const int t = t0 + tid;
        float qi = 1.f / fmaxf(sqrtf(g_ssq_q[t]), 1e-12f);
        float ki = 1.f / fmaxf(sqrtf(g_ssq_k[t]), 1e-12f);
        g_qinv[t] = qi;
        g_kinv[t] = ki;
        float a = g_adot[t] * qi * SCALEF;
        sw[tid] = a * qi;
        float av = a * a;
        #pragma unroll
        for (int o = 16; o > 0; o >>= 1) av += __shfl_xor_sync(0xffffffffu, av, o);
        if ((tid & 31) == 0) atomicAdd(&g_asumsq[b], av);
    }
    __syncthreads();

    const int d = tid;
    const float* Mb = g_qbuf + (size_t)t0 * DIM + d;
    float s = 0.f;
    #pragma unroll 4
    for (int n = 0; n < 128; n++) s = fmaf(sw[n], Mb[(size_t)n * DIM], s);
    atomicAdd(&g_gqraw[b * DIM + d], s);
}

__global__ __launch_bounds__(512) void gq_finalize(const float* __restrict__ w_beta) {
    const int b = blockIdx.x, d = threadIdx.x;
    __shared__ float sh[32];
    float inv = 1.f / fmaxf(sqrtf(g_asumsq[b]), 1e-12f);
    float v = g_gqraw[b * DIM + d] * inv;
    float mx = block_max(v, sh);
    float e = expf(v - mx);
    float s = block_sum(e, sh);
    float gq = e / s;
    g_gq[b * DIM + d] = gq;
    g_gw[b * DIM + d] = gq * w_beta[d];
}

// ---------------------------------------------------------------------------
// Fused beta + colsum1: per-token beta = SCALE*kinv*(kraw . gw), bsumsq
// atomics, then weighted colsum of RAW k into g_gkraw. grid (32,8), 512 thr.
// ---------------------------------------------------------------------------
__global__ __launch_bounds__(512) void beta_colsum1_fused() {
    __shared__ float sgw[DIM];
    __shared__ float sw[128];
    const int b = blockIdx.y, chunk = blockIdx.x;
    const int t0 = b * NSEQ + chunk * 128;
    const int tid = threadIdx.x, lane = tid & 31, wid = tid >> 5;

    sgw[tid] = g_gw[b * DIM + tid];
    __syncthreads();

    // pass 1: each warp computes beta for rows wid*8 .. wid*8+7
    float bsum = 0.f;
    #pragma unroll 1
    for (int r8 = 0; r8 < 8; r8++) {
        const int row = wid * 8 + r8;
        const float* kr = g_kbuf + (size_t)(t0 + row) * DIM;
        float dsum = 0.f;
        #pragma unroll
        for (int jj = 0; jj < 16; jj++)
            dsum = fmaf(kr[lane + 32 * jj], sgw[lane + 32 * jj], dsum);
        #pragma unroll
        for (int o = 16; o > 0; o >>= 1) dsum += __shfl_xor_sync(0xffffffffu, dsum, o);
        float ki = g_kinv[t0 + row];
        float bb = dsum * SCALEF * ki;
        if (lane == 0) sw[row] = bb * ki;
        bsum = fmaf(bb, bb, bsum);
    }
    if (lane == 0) atomicAdd(&g_bsumsq[b], bsum);
    __syncthreads();

    // pass 2: weighted colsum
    const int d = tid;
    const float* Mb = g_kbuf + (size_t)t0 * DIM + d;
    float s = 0.f;
    #pragma unroll 4
    for (int n = 0; n < 128; n++) s = fmaf(sw[n], Mb[(size_t)n * DIM], s);
    atomicAdd(&g_gkraw[b * DIM + d], s);
}

__global__ __launch_bounds__(512) void gk_finalize() {
    const int b = blockIdx.x, d = threadIdx.x;
    __shared__ float sh[32];
    float inv = 1.f / fmaxf(sqrtf(g_bsumsq[b]), 1e-12f);
    float v = g_gq[b * DIM + d] * g_gkraw[b * DIM + d] * inv;
    float mx = block_max(v, sh);
    float e = expf(v - mx);
    float s = block_sum(e, sh);
    g_gk[b * DIM + d] = e / s;
}

// ---------------------------------------------------------------------------
// Final GEMM (unchanged from R7): out = (gk.*kinv.*kraw + qinv.*qraw)@Wr + br
// 256 threads, warps 2x4, warp tile 64x32, scalar-LDS compute.
// ---------------------------------------------------------------------------
#define SM_FLOATS 4608
#define GEMM_SMEM (4 * SM_FLOATS * 4)

__device__ __forceinline__ void tile_compute(const float* __restrict__ As,
                                             const float* __restrict__ Bs,
                                             float acc[4][4][4],
                                             int warpM, int warpN, int g, int tg) {
    #pragma unroll
    for (int ks = 0; ks < 4; ks++) {
        uint32_t af[4][4], bf[4][2];
        #pragma unroll
        for (int mt = 0; mt < 4; mt++) {
            const float* p = As + (warpM * 64 + mt * 16 + g) * 36 + ks * 8 + tg;
            af[mt][0] = __float_as_uint(p[0]);
            af[mt][1] = __float_as_uint(p[8 * 36]);
            af[mt][2] = __float_as_uint(p[4]);
            af[mt][3] = __float_as_uint(p[8 * 36 + 4]);
        }
        #pragma unroll
        for (int nt = 0; nt < 4; nt++) {
            const float* p = Bs + (warpN * 32 + nt * 8 + g) * 36 + ks * 8 + tg;
            bf[nt][0] = __float_as_uint(p[0]);
            bf[nt][1] = __float_as_uint(p[4]);
        }
        #pragma unroll
        for (int mt = 0; mt < 4; mt++)
            #pragma unroll
            for (int nt = 0; nt < 4; nt++)
                mma8(acc[mt][nt], af[mt], bf[nt]);
    }
}

__global__ void __launch_bounds__(256)
mma_gemm_final(const float* __restrict__ bias, float* __restrict__ out) {
    extern __shared__ float sm[];
    float* bufA[2] = { sm, sm + 2 * SM_FLOATS };
    float* bufB[2] = { sm + SM_FLOATS, sm + 3 * SM_FLOATS };
    __shared__ float sbias[TOKD];
    __shared__ float sgk[DIM];
    __shared__ float sqinv[128];
    __shared__ float skinv[128];

    const int tid = threadIdx.x;
    const int lane = tid & 31, wid = tid >> 5;
    const int warpM = wid >> 2, warpN = wid & 3;
    const int g = lane >> 2, tg = lane & 3;
    const int m0 = blockIdx.y * 128, n0 = blockIdx.x * 128;
    const int b0 = m0 >> 12;
    const uint32_t sA[2] = { smem_u32(bufA[0]), smem_u32(bufA[1]) };
    const uint32_t sB[2] = { smem_u32(bufB[0]), smem_u32(bufB[1]) };

    for (int i = tid; i < TOKD; i += 256) sbias[i] = bias[i];
    for (int i = tid; i < DIM; i += 256) sgk[i] = g_gk[b0 * DIM + i];
    if (tid < 128) { sqinv[tid] = g_qinv[m0 + tid]; skinv[tid] = g_kinv[m0 + tid]; }

    float acc[4][4][4];
    #pragma unroll
    for (int a = 0; a < 4; a++)
        #pragma unroll
        for (int b = 0; b < 4; b++)
            #pragma unroll
            for (int c = 0; c < 4; c++) acc[a][b][c] = 0.f;

    auto load_B = [&](int c, int buf) {
        const int k0 = c * 32;
        #pragma unroll
        for (int l = 0; l < 4; l++) {
            int e = tid + l * 256, r = e >> 3, s = e & 7;
            cp16(sB[buf] + (r * 36 + s * 4) * 4, g_WrT + (size_t)(n0 + r) * DIM + k0 + s * 4);
        }
        cp_commit();
    };

    float4 kv[4], qv[4];
    auto fetch_A = [&](int c) {
        const int k0 = c * 32;
        #pragma unroll
        for (int l = 0; l < 4; l++) {
            int e = tid + l * 256, r = e >> 3, s = e & 7;
            kv[l] = *(const float4*)(g_kbuf + (size_t)(m0 + r) * DIM + k0 + s * 4);
            qv[l] = *(const float4*)(g_qbuf + (size_t)(m0 + r) * DIM + k0 + s * 4);
        }
    };
    auto sts_A = [&](int c, int buf) {
        const int k0 = c * 32;
        #pragma unroll
        for (int l = 0; l < 4; l++) {
            int e = tid + l * 256, r = e >> 3, s = e & 7;
            float qi = sqinv[r], ksc = skinv[r];
            int k = k0 + s * 4;
            float v0 = fmaf(sgk[k + 0] * ksc, kv[l].x, qi * qv[l].x);
            float v1 = fmaf(sgk[k + 1] * ksc, kv[l].y, qi * qv[l].y);
            float v2 = fmaf(sgk[k + 2] * ksc, kv[l].z, qi * qv[l].z);
            float v3 = fmaf(sgk[k + 3] * ksc, kv[l].w, qi * qv[l].w);
            sts128(sA[buf] + (r * 36 + s * 4) * 4,
                   f2tf32(v0), f2tf32(v1), f2tf32(v2), f2tf32(v3));
        }
    };

    fetch_A(0);
    load_B(0, 0);
    __syncthreads();
    #pragma unroll 1
    for (int c = 0; c < 16; c++) {
        sts_A(c, c & 1);
        if (c + 1 < 16) { fetch_A(c + 1); load_B(c + 1, (c + 1) & 1); cp_wait1(); }
        else cp_wait0();
        __syncthreads();
        tile_compute(bufA[c & 1], bufB[c & 1], acc, warpM, warpN, g, tg);
        __syncthreads();
    }

    #pragma unroll
    for (int mt = 0; mt < 4; mt++) {
        const int r1 = m0 + warpM * 64 + mt * 16 + g;
        const int r2 = r1 + 8;
        #pragma unroll
        for (int nt = 0; nt < 4; nt++) {
            const int col = n0 + warpN * 32 + nt * 8 + 2 * tg;
            float2 o1, o2;
            o1.x = acc[mt][nt][0] + sbias[col];
            o1.y = acc[mt][nt][1] + sbias[col + 1];
            o2.x = acc[mt][nt][2] + sbias[col];
            o2.y = acc[mt][nt][3] + sbias[col + 1];
            *(float2*)(out + (size_t)r1 * TOKD + col) = o1;
            *(float2*)(out + (size_t)r2 * TOKD + col) = o2;
        }
    }
}

// ---------------------------------------------------------------------------
// Launch
// ---------------------------------------------------------------------------
extern "C" void kernel_launch(void* const* d_in, const int* in_sizes, int n_in,
                              void* d_out, int out_size) {
    const float* x  = (const float*)d_in[0];
    const float* Wq = (const float*)d_in[1];
    const float* bq = (const float*)d_in[2];
    const float* Wk = (const float*)d_in[3];
    const float* bk = (const float*)d_in[4];
    const float* Wr = (const float*)d_in[5];
    const float* br = (const float*)d_in[6];
    const float* wa = (const float*)d_in[7];
    const float* wb = (const float*)d_in[8];
    float* out = (float*)d_out;

    cudaFuncSetAttribute(mma_gemm_qk2,  cudaFuncAttributeMaxDynamicSharedMemorySize, QK_SMEM);
    cudaFuncSetAttribute(mma_gemm_final, cudaFuncAttributeMaxDynamicSharedMemorySize, GEMM_SMEM);

    zero_scratch<<<128, 256>>>();
    transpose_w<<<dim3(16, 16, 3), dim3(32, 32)>>>(Wq, Wk, Wr);
    mma_gemm_qk2<<<dim3(8, 256), 128, QK_SMEM>>>(x, bq, bk, wa);
    colsum0_fused<<<dim3(32, BATCH), 512>>>();
    gq_finalize<<<BATCH, 512>>>(wb);
    beta_colsum1_fused<<<dim3(32, BATCH), 512>>>();
    gk_finalize<<<BATCH, 512>>>();
    mma_gemm_final<<<dim3(2, 256), 256, GEMM_SMEM>>>(br, out);
}

// round 9
// speedup vs baseline: 3.3559x; 1.0670x over previous
#include <cuda_runtime.h>
#include <math.h>
#include <stdint.h>

// ---------------------------------------------------------------------------
// Problem constants
// ---------------------------------------------------------------------------
#define BATCH  8
#define NSEQ   4096
#define NTOK   (BATCH * NSEQ)   // 32768
#define DIM    512
#define TOKD   256
#define SCALEF 0.0625f          // 256^-0.5

// ---------------------------------------------------------------------------
// Device scratch
// ---------------------------------------------------------------------------
__device__ __align__(256) float g_qbuf[(size_t)NTOK * DIM];   // RAW q (bias added, NOT normalized)
__device__ __align__(256) float g_kbuf[(size_t)NTOK * DIM];   // RAW k
__device__ __align__(256) float g_WqT[DIM * DIM];             // [n][k], tf32-rounded
__device__ __align__(256) float g_WkT[DIM * DIM];
__device__ __align__(256) float g_WrT[TOKD * DIM];
__device__ __align__(256) float g_ssq_q[NTOK];
__device__ __align__(256) float g_ssq_k[NTOK];
__device__ __align__(256) float g_adot [NTOK];
__device__ __align__(256) float g_qinv [NTOK];
__device__ __align__(256) float g_kinv [NTOK];
__device__ __align__(256) float g_asumsq[BATCH];
__device__ __align__(256) float g_bsumsq[BATCH];
__device__ __align__(256) float g_gqraw[BATCH * DIM];
__device__ __align__(256) float g_gkraw[BATCH * DIM];
__device__ __align__(256) float g_gq[BATCH * DIM];
__device__ __align__(256) float g_gw[BATCH * DIM];
__device__ __align__(256) float g_gk[BATCH * DIM];

// ---------------------------------------------------------------------------
// PTX helpers
// ---------------------------------------------------------------------------
__device__ __forceinline__ uint32_t smem_u32(const void* p) {
    uint32_t a;
    asm("{ .reg .u64 t; cvta.to.shared.u64 t, %1; cvt.u32.u64 %0, t; }" : "=r"(a) : "l"(p));
    return a;
}
__device__ __forceinline__ uint32_t f2tf32(float f) {
    uint32_t u;
    asm("cvt.rna.tf32.f32 %0, %1;" : "=r"(u) : "f"(f));
    return u;
}
__device__ __forceinline__ void sts128(uint32_t a, uint32_t x, uint32_t y, uint32_t z, uint32_t w) {
    asm volatile("st.shared.v4.b32 [%0], {%1,%2,%3,%4};" :: "r"(a), "r"(x), "r"(y), "r"(z), "r"(w) : "memory");
}
__device__ __forceinline__ void cp16(uint32_t saddr, const void* g) {
    asm volatile("cp.async.cg.shared.global [%0], [%1], 16;" :: "r"(saddr), "l"(g) : "memory");
}
__device__ __forceinline__ void cp_commit() { asm volatile("cp.async.commit_group;" ::: "memory"); }
__device__ __forceinline__ void cp_wait0()  { asm volatile("cp.async.wait_group 0;" ::: "memory"); }
__device__ __forceinline__ void cp_wait1()  { asm volatile("cp.async.wait_group 1;" ::: "memory"); }

// mma.sync m16n8k8 tf32
__device__ __forceinline__ void mma8(float* d, const uint32_t* a, const uint32_t* b) {
    asm volatile(
        "mma.sync.aligned.m16n8k8.row.col.f32.tf32.tf32.f32 "
        "{%0,%1,%2,%3}, {%4,%5,%6,%7}, {%8,%9}, {%0,%1,%2,%3};"
        : "+f"(d[0]), "+f"(d[1]), "+f"(d[2]), "+f"(d[3])
        : "r"(a[0]), "r"(a[1]), "r"(a[2]), "r"(a[3]), "r"(b[0]), "r"(b[1]));
}
// ldmatrix x4: 4 8x8 b16 tiles == 4 8x4 fp32 tiles; lane -> (row i>>2, col i&3)
__device__ __forceinline__ void ldsm4(uint32_t* r, uint32_t addr) {
    asm volatile("ldmatrix.sync.aligned.m8n8.x4.shared.b16 {%0,%1,%2,%3}, [%4];"
        : "=r"(r[0]), "=r"(r[1]), "=r"(r[2]), "=r"(r[3]) : "r"(addr));
}

// ---------------------------------------------------------------------------
// Block reductions
// ---------------------------------------------------------------------------
__device__ __forceinline__ float block_sum(float v, float* sh) {
    #pragma unroll
    for (int o = 16; o > 0; o >>= 1) v += __shfl_xor_sync(0xffffffffu, v, o);
    int w = threadIdx.x >> 5;
    if ((threadIdx.x & 31) == 0) sh[w] = v;
    __syncthreads();
    int nw = blockDim.x >> 5;
    if (threadIdx.x < 32) {
        float s = (threadIdx.x < nw) ? sh[threadIdx.x] : 0.f;
        #pragma unroll
        for (int o = 16; o > 0; o >>= 1) s += __shfl_xor_sync(0xffffffffu, s, o);
        if (threadIdx.x == 0) sh[0] = s;
    }
    __syncthreads();
    float r = sh[0];
    __syncthreads();
    return r;
}
__device__ __forceinline__ float block_max(float v, float* sh) {
    #pragma unroll
    for (int o = 16; o > 0; o >>= 1) v = fmaxf(v, __shfl_xor_sync(0xffffffffu, v, o));
    int w = threadIdx.x >> 5;
    if ((threadIdx.x & 31) == 0) sh[w] = v;
    __syncthreads();
    int nw = blockDim.x >> 5;
    if (threadIdx.x < 32) {
        float s = (threadIdx.x < nw) ? sh[threadIdx.x] : -3.4e38f;
        #pragma unroll
        for (int o = 16; o > 0; o >>= 1) s = fmaxf(s, __shfl_xor_sync(0xffffffffu, s, o));
        if (threadIdx.x == 0) sh[0] = s;
    }
    __syncthreads();
    float r = sh[0];
    __syncthreads();
    return r;
}

// ---------------------------------------------------------------------------
// zero accumulators
// ---------------------------------------------------------------------------
__global__ void zero_scratch() {
    int i = blockIdx.x * blockDim.x + threadIdx.x;
    if (i < NTOK) { g_ssq_q[i] = 0.f; g_ssq_k[i] = 0.f; g_adot[i] = 0.f; }
    if (i < BATCH * DIM) { g_gqraw[i] = 0.f; g_gkraw[i] = 0.f; }
    if (i < BATCH) { g_asumsq[i] = 0.f; g_bsumsq[i] = 0.f; }
}

// ---------------------------------------------------------------------------
// Transpose weights [K,N] -> [N,K] with tf32 pre-rounding
// ---------------------------------------------------------------------------
__global__ void transpose_w(const float* __restrict__ Wq, const float* __restrict__ Wk,
                            const float* __restrict__ Wr) {
    __shared__ float t[32][33];
    int z = blockIdx.z;
    const float* src = (z == 0) ? Wq : (z == 1) ? Wk : Wr;
    float* dst = (z == 0) ? g_WqT : (z == 1) ? g_WkT : g_WrT;
    int ncols = (z == 2) ? TOKD : DIM;
    int k0 = blockIdx.y * 32, n0 = blockIdx.x * 32;
    if (n0 >= ncols) return;
    t[threadIdx.y][threadIdx.x] = src[(size_t)(k0 + threadIdx.y) * ncols + n0 + threadIdx.x];
    __syncthreads();
    dst[(size_t)(n0 + threadIdx.y) * DIM + k0 + threadIdx.x] =
        __uint_as_float(f2tf32(t[threadIdx.x][threadIdx.y]));
}

// ---------------------------------------------------------------------------
// ldmatrix-based tile compute: 4 warps (2x2), warp tile 64x64, BK=32,
// smem rows padded to 36 floats
// ---------------------------------------------------------------------------
__device__ __forceinline__ void tile_compute_ldsm(uint32_t sAb, uint32_t sBb,
                                                  float acc[4][8][4],
                                                  int lane, int warpM, int warpN) {
    const int j = lane >> 3, i = lane & 7;
    const int arow = warpM * 64 + (j & 1) * 8 + i;
    const int acol = (j >> 1) * 4;
    const int brow = warpN * 64 + ((j >> 1) & 1) * 8 + i;
    const int bcol = (j & 1) * 4;
    #pragma unroll
    for (int ks = 0; ks < 4; ks++) {
        uint32_t af[4][4], bf[4][4];
        #pragma unroll
        for (int mt = 0; mt < 4; mt++)
            ldsm4(af[mt], sAb + ((arow + mt * 16) * 36 + ks * 8 + acol) * 4);
        #pragma unroll
        for (int ntp = 0; ntp < 4; ntp++)
            ldsm4(bf[ntp], sBb + ((brow + ntp * 16) * 36 + ks * 8 + bcol) * 4);
        #pragma unroll
        for (int mt = 0; mt < 4; mt++)
            #pragma unroll
            for (int nt = 0; nt < 8; nt++)
                mma8(acc[mt][nt], af[mt], &bf[nt >> 1][(nt & 1) * 2]);
    }
}

// ---------------------------------------------------------------------------
// Fused q+k GEMM (unchanged from R8): grid (8, 256), 128 threads.
// ---------------------------------------------------------------------------
#define QK_SMF  4608                    // 128*36 floats per tile buffer
#define QK_SMEM (4 * QK_SMF * 4)        // 73728 bytes (A0,B0,A1,B1)

__global__ void __launch_bounds__(128, 2)
mma_gemm_qk2(const float* __restrict__ X,
             const float* __restrict__ bq, const float* __restrict__ bk,
             const float* __restrict__ w_alpha) {
    extern __shared__ float sm[];
    __shared__ float sbias[DIM];
    __shared__ float swa[DIM];

    const int isq = (blockIdx.x < 4);
    const int n0 = (blockIdx.x & 3) * 128;
    const int m0 = blockIdx.y * 128;
    const float* __restrict__ WT   = isq ? g_WqT : g_WkT;
    const float* __restrict__ bias = isq ? bq : bk;
    float* __restrict__ C   = isq ? g_qbuf : g_kbuf;
    float* __restrict__ ssq = isq ? g_ssq_q : g_ssq_k;

    const int tid = threadIdx.x, lane = tid & 31, wid = tid >> 5;
    const int warpM = wid >> 1, warpN = wid & 1;
    const uint32_t sA[2] = { smem_u32(sm),           smem_u32(sm + 2 * QK_SMF) };
    const uint32_t sB[2] = { smem_u32(sm + QK_SMF),  smem_u32(sm + 3 * QK_SMF) };

    for (int i = tid; i < DIM; i += 128) { sbias[i] = bias[i]; swa[i] = w_alpha[i]; }

    float acc[4][8][4];
    #pragma unroll
    for (int a = 0; a < 4; a++)
        #pragma unroll
        for (int b = 0; b < 8; b++)
            #pragma unroll
            for (int c = 0; c < 4; c++) acc[a][b][c] = 0.f;

    auto load_tile = [&](int c, int buf) {
        const int k0 = c * 32;
        #pragma unroll
        for (int l = 0; l < 8; l++) {
            int e = tid + l * 128, r = e >> 3, s = e & 7;
            cp16(sA[buf] + (r * 36 + s * 4) * 4, X + (size_t)(m0 + r) * DIM + k0 + s * 4);
        }
        #pragma unroll
        for (int l = 0; l < 8; l++) {
            int e = tid + l * 128, r = e >> 3, s = e & 7;
            cp16(sB[buf] + (r * 36 + s * 4) * 4, WT + (size_t)(n0 + r) * DIM + k0 + s * 4);
        }
        cp_commit();
    };

    load_tile(0, 0);
    #pragma unroll 1
    for (int c = 0; c < 16; c++) {
        if (c + 1 < 16) { load_tile(c + 1, (c + 1) & 1); cp_wait1(); }
        else cp_wait0();
        __syncthreads();
        tile_compute_ldsm(sA[c & 1], sB[c & 1], acc, lane, warpM, warpN);
        __syncthreads();
    }

    const int g = lane >> 2, tg = lane & 3;
    #pragma unroll
    for (int mt = 0; mt < 4; mt++) {
        const int r1 = m0 + warpM * 64 + mt * 16 + g;
        const int r2 = r1 + 8;
        float s1 = 0.f, s2 = 0.f, a1 = 0.f, a2 = 0.f;
        #pragma unroll
        for (int nt = 0; nt < 8; nt++) {
            const int col = n0 + warpN * 64 + nt * 8 + 2 * tg;
            float v0 = acc[mt][nt][0] + sbias[col];
            float v1 = acc[mt][nt][1] + sbias[col + 1];
            float v2 = acc[mt][nt][2] + sbias[col];
            float v3 = acc[mt][nt][3] + sbias[col + 1];
            *(float2*)(C + (size_t)r1 * DIM + col) = make_float2(v0, v1);
            *(float2*)(C + (size_t)r2 * DIM + col) = make_float2(v2, v3);
            s1 = fmaf(v0, v0, fmaf(v1, v1, s1));
            s2 = fmaf(v2, v2, fmaf(v3, v3, s2));
            if (isq) {
                a1 = fmaf(v0, swa[col], fmaf(v1, swa[col + 1], a1));
                a2 = fmaf(v2, swa[col], fmaf(v3, swa[col + 1], a2));
            }
        }
        s1 += __shfl_xor_sync(0xffffffffu, s1, 1); s1 += __shfl_xor_sync(0xffffffffu, s1, 2);
        s2 += __shfl_xor_sync(0xffffffffu, s2, 1); s2 += __shfl_xor_sync(0xffffffffu, s2, 2);
        if (isq) {
            a1 += __shfl_xor_sync(0xffffffffu, a1, 1); a1 += __shfl_xor_sync(0xffffffffu, a1, 2);
            a2 += __shfl_xor_sync(0xffffffffu, a2, 1); a2 += __shfl_xor_sync(0xffffffffu, a2, 2);
        }
        if (tg == 0) {
            atomicAdd(&ssq[r1], s1);
            atomicAdd(&ssq[r2], s2);
            if (isq) { atomicAdd(&g_adot[r1], a1); atomicAdd(&g_adot[r2], a2); }
        }
    }
}

// ---------------------------------------------------------------------------
// Fused finalize_tok + colsum0. 64-row chunks, 4-way ILP accumulators.
// grid (64, 8), 512 threads.
// ---------------------------------------------------------------------------
__global__ __launch_bounds__(512) void colsum0_fused() {
    __shared__ float sw[64];
    const int b = blockIdx.y, chunk = blockIdx.x;
    const int t0 = b * NSEQ + chunk * 64;
    const int tid = threadIdx.x;

    if (tid < 64) {
        const int t = t0 + tid;
        float qi = 1.f / fmaxf(sqrtf(g_ssq_q[t]), 1e-12f);
        float ki = 1.f / fmaxf(sqrtf(g_ssq_k[t]), 1e-12f);
        g_qinv[t] = qi;
        g_kinv[t] = ki;
        float a = g_adot[t] * qi * SCALEF;
        sw[tid] = a * qi;
        float av = a * a;
        #pragma unroll
        for (int o = 16; o > 0; o >>= 1) av += __shfl_xor_sync(0xffffffffu, av, o);
        if ((tid & 31) == 0) atomicAdd(&g_asumsq[b], av);
    }
    __syncthreads();

    const int d = tid;
    const float* Mb = g_qbuf + (size_t)t0 * DIM + d;
    float s0 = 0.f, s1 = 0.f, s2 = 0.f, s3 = 0.f;
    #pragma unroll
    for (int n = 0; n < 64; n += 4) {
        s0 = fmaf(sw[n + 0], Mb[(size_t)(n + 0) * DIM], s0);
        s1 = fmaf(sw[n + 1], Mb[(size_t)(n + 1) * DIM], s1);
        s2 = fmaf(sw[n + 2], Mb[(size_t)(n + 2) * DIM], s2);
        s3 = fmaf(sw[n + 3], Mb[(size_t)(n + 3) * DIM], s3);
    }
    atomicAdd(&g_gqraw[b * DIM + d], (s0 + s1) + (s2 + s3));
}

__global__ __launch_bounds__(512) void gq_finalize(const float* __restrict__ w_beta) {
    const int b = blockIdx.x, d = threadIdx.x;
    __shared__ float sh[32];
    float inv = 1.f / fmaxf(sqrtf(g_asumsq[b]), 1e-12f);
    float v = g_gqraw[b * DIM + d] * inv;
    float mx = block_max(v, sh);
    float e = expf(v - mx);
    float s = block_sum(e, sh);
    float gq = e / s;
    g_gq[b * DIM + d] = gq;
    g_gw[b * DIM + d] = gq * w_beta[d];
}

// ---------------------------------------------------------------------------
// Fused beta + colsum1. 64-row chunks: 16 warps x 4 rows each for beta,
// then 4-way ILP colsum. grid (64, 8), 512 threads.
// ---------------------------------------------------------------------------
__global__ __launch_bounds__(512) void beta_colsum1_fused() {
    __shared__ float sgw[DIM];
    __shared__ float sw[64];
    const int b = blockIdx.y, chunk = blockIdx.x;
    const int t0 = b * NSEQ + chunk * 64;
    const int tid = threadIdx.x, lane = tid & 31, wid = tid >> 5;

    sgw[tid] = g_gw[b * DIM + tid];
    __syncthreads();

    // beta for rows wid*4 .. wid*4+3 (row-interleaved loads for MLP)
    {
        const int row0 = wid * 4;
        float d0 = 0.f, d1 = 0.f, d2 = 0.f, d3 = 0.f;
        const float* k0p = g_kbuf + (size_t)(t0 + row0 + 0) * DIM;
        const float* k1p = g_kbuf + (size_t)(t0 + row0 + 1) * DIM;
        const float* k2p = g_kbuf + (size_t)(t0 + row0 + 2) * DIM;
        const float* k3p = g_kbuf + (size_t)(t0 + row0 + 3) * DIM;
        #pragma unroll
        for (int jj = 0; jj < 16; jj++) {
            const int idx = lane + 32 * jj;
            const float w = sgw[idx];
            d0 = fmaf(k0p[idx], w, d0);
            d1 = fmaf(k1p[idx], w, d1);
            d2 = fmaf(k2p[idx], w, d2);
            d3 = fmaf(k3p[idx], w, d3);
        }
        #pragma unroll
        for (int o = 16; o > 0; o >>= 1) {
            d0 += __shfl_xor_sync(0xffffffffu, d0, o);
            d1 += __shfl_xor_sync(0xffffffffu, d1, o);
            d2 += __shfl_xor_sync(0xffffffffu, d2, o);
            d3 += __shfl_xor_sync(0xffffffffu, d3, o);
        }
        if (lane == 0) {
            float bsum = 0.f;
            float dv[4] = { d0, d1, d2, d3 };
            #pragma unroll
            for (int r = 0; r < 4; r++) {
                float ki = g_kinv[t0 + row0 + r];
                float bb = dv[r] * SCALEF * ki;
                sw[row0 + r] = bb * ki;
                bsum = fmaf(bb, bb, bsum);
            }
            atomicAdd(&g_bsumsq[b], bsum);
        }
    }
    __syncthreads();

    const int d = tid;
    const float* Mb = g_kbuf + (size_t)t0 * DIM + d;
    float s0 = 0.f, s1 = 0.f, s2 = 0.f, s3 = 0.f;
    #pragma unroll
    for (int n = 0; n < 64; n += 4) {
        s0 = fmaf(sw[n + 0], Mb[(size_t)(n + 0) * DIM], s0);
        s1 = fmaf(sw[n + 1], Mb[(size_t)(n + 1) * DIM], s1);
        s2 = fmaf(sw[n + 2], Mb[(size_t)(n + 2) * DIM], s2);
        s3 = fmaf(sw[n + 3], Mb[(size_t)(n + 3) * DIM], s3);
    }
    atomicAdd(&g_gkraw[b * DIM + d], (s0 + s1) + (s2 + s3));
}

__global__ __launch_bounds__(512) void gk_finalize() {
    const int b = blockIdx.x, d = threadIdx.x;
    __shared__ float sh[32];
    float inv = 1.f / fmaxf(sqrtf(g_bsumsq[b]), 1e-12f);
    float v = g_gq[b * DIM + d] * g_gkraw[b * DIM + d] * inv;
    float mx = block_max(v, sh);
    float e = expf(v - mx);
    float s = block_sum(e, sh);
    g_gk[b * DIM + d] = e / s;
}

// ---------------------------------------------------------------------------
// Final GEMM (ldsm4 redesign): out = (gk.*kinv.*kraw + qinv.*qraw)@Wr + br
// 128 threads, 4 warps 2x2 at 64x64, grid (2, 256).
// ---------------------------------------------------------------------------
__global__ void __launch_bounds__(128, 2)
mma_gemm_final(const float* __restrict__ bias, float* __restrict__ out) {
    extern __shared__ float sm[];
    __shared__ float sbias[TOKD];
    __shared__ float sgk[DIM];
    __shared__ float sqinv[128];
    __shared__ float skinv[128];

    const int tid = threadIdx.x, lane = tid & 31, wid = tid >> 5;
    const int warpM = wid >> 1, warpN = wid & 1;
    const int m0 = blockIdx.y * 128, n0 = blockIdx.x * 128;
    const int b0 = m0 >> 12;
    const uint32_t sA[2] = { smem_u32(sm),          smem_u32(sm + 2 * QK_SMF) };
    const uint32_t sB[2] = { smem_u32(sm + QK_SMF), smem_u32(sm + 3 * QK_SMF) };

    for (int i = tid; i < TOKD; i += 128) sbias[i] = bias[i];
    for (int i = tid; i < DIM; i += 128) sgk[i] = g_gk[b0 * DIM + i];
    if (tid < 128) { sqinv[tid] = g_qinv[m0 + tid]; skinv[tid] = g_kinv[m0 + tid]; }

    float acc[4][8][4];
    #pragma unroll
    for (int a = 0; a < 4; a++)
        #pragma unroll
        for (int b = 0; b < 8; b++)
            #pragma unroll
            for (int c = 0; c < 4; c++) acc[a][b][c] = 0.f;

    auto load_B = [&](int c, int buf) {
        const int k0 = c * 32;
        #pragma unroll
        for (int l = 0; l < 8; l++) {
            int e = tid + l * 128, r = e >> 3, s = e & 7;
            cp16(sB[buf] + (r * 36 + s * 4) * 4, g_WrT + (size_t)(n0 + r) * DIM + k0 + s * 4);
        }
        cp_commit();
    };

    float4 kv[8], qv[8];
    auto fetch_A = [&](int c) {
        const int k0 = c * 32;
        #pragma unroll
        for (int l = 0; l < 8; l++) {
            int e = tid + l * 128, r = e >> 3, s = e & 7;
            kv[l] = *(const float4*)(g_kbuf + (size_t)(m0 + r) * DIM + k0 + s * 4);
            qv[l] = *(const float4*)(g_qbuf + (size_t)(m0 + r) * DIM + k0 + s * 4);
        }
    };
    auto sts_A = [&](int c, int buf) {
        const int k0 = c * 32;
        #pragma unroll
        for (int l = 0; l < 8; l++) {
            int e = tid + l * 128, r = e >> 3, s = e & 7;
            float qi = sqinv[r], ksc = skinv[r];
            int k = k0 + s * 4;
            float v0 = fmaf(sgk[k + 0] * ksc, kv[l].x, qi * qv[l].x);
            float v1 = fmaf(sgk[k + 1] * ksc, kv[l].y, qi * qv[l].y);
            float v2 = fmaf(sgk[k + 2] * ksc, kv[l].z, qi * qv[l].z);
            float v3 = fmaf(sgk[k + 3] * ksc, kv[l].w, qi * qv[l].w);
            sts128(sA[buf] + (r * 36 + s * 4) * 4,
                   f2tf32(v0), f2tf32(v1), f2tf32(v2), f2tf32(v3));
        }
    };

    fetch_A(0);
    load_B(0, 0);
    __syncthreads();                 // sqinv/sgk ready before first sts_A
    #pragma unroll 1
    for (int c = 0; c < 16; c++) {
        sts_A(c, c & 1);
        if (c + 1 < 16) { fetch_A(c + 1); load_B(c + 1, (c + 1) & 1); cp_wait1(); }
        else cp_wait0();
        __syncthreads();
        tile_compute_ldsm(sA[c & 1], sB[c & 1], acc, lane, warpM, warpN);
        __syncthreads();
    }

    const int g = lane >> 2, tg = lane & 3;
    #pragma unroll
    for (int mt = 0; mt < 4; mt++) {
        const int r1 = m0 + warpM * 64 + mt * 16 + g;
        const int r2 = r1 + 8;
        #pragma unroll
        for (int nt = 0; nt < 8; nt++) {
            const int col = n0 + warpN * 64 + nt * 8 + 2 * tg;
            float2 o1, o2;
            o1.x = acc[mt][nt][0] + sbias[col];
            o1.y = acc[mt][nt][1] + sbias[col + 1];
            o2.x = acc[mt][nt][2] + sbias[col];
            o2.y = acc[mt][nt][3] + sbias[col + 1];
            *(float2*)(out + (size_t)r1 * TOKD + col) = o1;
            *(float2*)(out + (size_t)r2 * TOKD + col) = o2;
        }
    }
}

// ---------------------------------------------------------------------------
// Launch
// ---------------------------------------------------------------------------
extern "C" void kernel_launch(void* const* d_in, const int* in_sizes, int n_in,
                              void* d_out, int out_size) {
    const float* x  = (const float*)d_in[0];
    const float* Wq = (const float*)d_in[1];
    const float* bq = (const float*)d_in[2];
    const float* Wk = (const float*)d_in[3];
    const float* bk = (const float*)d_in[4];
    const float* Wr = (const float*)d_in[5];
    const float* br = (const float*)d_in[6];
    const float* wa = (const float*)d_in[7];
    const float* wb = (const float*)d_in[8];
    float* out = (float*)d_out;

    cudaFuncSetAttribute(mma_gemm_qk2,   cudaFuncAttributeMaxDynamicSharedMemorySize, QK_SMEM);
    cudaFuncSetAttribute(mma_gemm_final, cudaFuncAttributeMaxDynamicSharedMemorySize, QK_SMEM);

    zero_scratch<<<128, 256>>>();
    transpose_w<<<dim3(16, 16, 3), dim3(32, 32)>>>(Wq, Wk, Wr);
    mma_gemm_qk2<<<dim3(8, 256), 128, QK_SMEM>>>(x, bq, bk, wa);
    colsum0_fused<<<dim3(64, BATCH), 512>>>();
    gq_finalize<<<BATCH, 512>>>(wb);
    beta_colsum1_fused<<<dim3(64, BATCH), 512>>>();
    gk_finalize<<<BATCH, 512>>>();
    mma_gemm_final<<<dim3(2, 256), 128, QK_SMEM>>>(br, out);
}

// round 10
// speedup vs baseline: 3.5144x; 1.0472x over previous
#include <cuda_runtime.h>
#include <math.h>
#include <stdint.h>

// ---------------------------------------------------------------------------
// Problem constants
// ---------------------------------------------------------------------------
#define BATCH  8
#define NSEQ   4096
#define NTOK   (BATCH * NSEQ)   // 32768
#define DIM    512
#define TOKD   256
#define SCALEF 0.0625f          // 256^-0.5

// ---------------------------------------------------------------------------
// Device scratch
// ---------------------------------------------------------------------------
__device__ __align__(256) float g_qbuf[(size_t)NTOK * DIM];   // RAW q (bias added, NOT normalized)
__device__ __align__(256) float g_kbuf[(size_t)NTOK * DIM];   // RAW k
__device__ __align__(256) float g_WqT[DIM * DIM];             // [n][k], tf32-rounded
__device__ __align__(256) float g_WkT[DIM * DIM];
__device__ __align__(256) float g_WrT[TOKD * DIM];
__device__ __align__(256) float g_ssq_q[NTOK];
__device__ __align__(256) float g_ssq_k[NTOK];
__device__ __align__(256) float g_adot [NTOK];
__device__ __align__(256) float g_qinv [NTOK];
__device__ __align__(256) float g_kinv [NTOK];
__device__ __align__(256) float g_asumsq[BATCH];
__device__ __align__(256) float g_bsumsq[BATCH];
__device__ __align__(256) float g_gqraw[BATCH * DIM];
__device__ __align__(256) float g_gkraw[BATCH * DIM];

// ---------------------------------------------------------------------------
// PTX helpers
// ---------------------------------------------------------------------------
__device__ __forceinline__ uint32_t smem_u32(const void* p) {
    uint32_t a;
    asm("{ .reg .u64 t; cvta.to.shared.u64 t, %1; cvt.u32.u64 %0, t; }" : "=r"(a) : "l"(p));
    return a;
}
__device__ __forceinline__ uint32_t f2tf32(float f) {
    uint32_t u;
    asm("cvt.rna.tf32.f32 %0, %1;" : "=r"(u) : "f"(f));
    return u;
}
__device__ __forceinline__ void sts128(uint32_t a, uint32_t x, uint32_t y, uint32_t z, uint32_t w) {
    asm volatile("st.shared.v4.b32 [%0], {%1,%2,%3,%4};" :: "r"(a), "r"(x), "r"(y), "r"(z), "r"(w) : "memory");
}
__device__ __forceinline__ void cp16(uint32_t saddr, const void* g) {
    asm volatile("cp.async.cg.shared.global [%0], [%1], 16;" :: "r"(saddr), "l"(g) : "memory");
}
__device__ __forceinline__ void cp_commit() { asm volatile("cp.async.commit_group;" ::: "memory"); }
__device__ __forceinline__ void cp_wait0()  { asm volatile("cp.async.wait_group 0;" ::: "memory"); }
__device__ __forceinline__ void cp_wait1()  { asm volatile("cp.async.wait_group 1;" ::: "memory"); }

// mma.sync m16n8k8 tf32
__device__ __forceinline__ void mma8(float* d, const uint32_t* a, const uint32_t* b) {
    asm volatile(
        "mma.sync.aligned.m16n8k8.row.col.f32.tf32.tf32.f32 "
        "{%0,%1,%2,%3}, {%4,%5,%6,%7}, {%8,%9}, {%0,%1,%2,%3};"
        : "+f"(d[0]), "+f"(d[1]), "+f"(d[2]), "+f"(d[3])
        : "r"(a[0]), "r"(a[1]), "r"(a[2]), "r"(a[3]), "r"(b[0]), "r"(b[1]));
}
// ldmatrix x4: 4 8x8 b16 tiles == 4 8x4 fp32 tiles; lane -> (row i>>2, col i&3)
__device__ __forceinline__ void ldsm4(uint32_t* r, uint32_t addr) {
    asm volatile("ldmatrix.sync.aligned.m8n8.x4.shared.b16 {%0,%1,%2,%3}, [%4];"
        : "=r"(r[0]), "=r"(r[1]), "=r"(r[2]), "=r"(r[3]) : "r"(addr));
}

// ---------------------------------------------------------------------------
// Block reductions (blockDim-aware)
// ---------------------------------------------------------------------------
__device__ __forceinline__ float block_sum(float v, float* sh) {
    #pragma unroll
    for (int o = 16; o > 0; o >>= 1) v += __shfl_xor_sync(0xffffffffu, v, o);
    int w = threadIdx.x >> 5;
    if ((threadIdx.x & 31) == 0) sh[w] = v;
    __syncthreads();
    int nw = blockDim.x >> 5;
    if (threadIdx.x < 32) {
        float s = (threadIdx.x < nw) ? sh[threadIdx.x] : 0.f;
        #pragma unroll
        for (int o = 16; o > 0; o >>= 1) s += __shfl_xor_sync(0xffffffffu, s, o);
        if (threadIdx.x == 0) sh[0] = s;
    }
    __syncthreads();
    float r = sh[0];
    __syncthreads();
    return r;
}
__device__ __forceinline__ float block_max(float v, float* sh) {
    #pragma unroll
    for (int o = 16; o > 0; o >>= 1) v = fmaxf(v, __shfl_xor_sync(0xffffffffu, v, o));
    int w = threadIdx.x >> 5;
    if ((threadIdx.x & 31) == 0) sh[w] = v;
    __syncthreads();
    int nw = blockDim.x >> 5;
    if (threadIdx.x < 32) {
        float s = (threadIdx.x < nw) ? sh[threadIdx.x] : -3.4e38f;
        #pragma unroll
        for (int o = 16; o > 0; o >>= 1) s = fmaxf(s, __shfl_xor_sync(0xffffffffu, s, o));
        if (threadIdx.x == 0) sh[0] = s;
    }
    __syncthreads();
    float r = sh[0];
    __syncthreads();
    return r;
}

// ---------------------------------------------------------------------------
// Transpose weights [K,N] -> [N,K] with tf32 pre-rounding. Also zeroes the
// accumulator scratch (fused former zero_scratch; no ordering needed within
// this kernel — consumers are later kernels).
// ---------------------------------------------------------------------------
__global__ void transpose_w(const float* __restrict__ Wq, const float* __restrict__ Wk,
                            const float* __restrict__ Wr) {
    __shared__ float t[32][33];
    // fused zeroing
    {
        int flat = (blockIdx.z * gridDim.y + blockIdx.y) * gridDim.x + blockIdx.x;
        int gid = flat * 1024 + threadIdx.y * 32 + threadIdx.x;
        if (gid < NTOK) { g_ssq_q[gid] = 0.f; g_ssq_k[gid] = 0.f; g_adot[gid] = 0.f; }
        if (gid < BATCH * DIM) { g_gqraw[gid] = 0.f; g_gkraw[gid] = 0.f; }
        if (gid < BATCH) { g_asumsq[gid] = 0.f; g_bsumsq[gid] = 0.f; }
    }
    int z = blockIdx.z;
    const float* src = (z == 0) ? Wq : (z == 1) ? Wk : Wr;
    float* dst = (z == 0) ? g_WqT : (z == 1) ? g_WkT : g_WrT;
    int ncols = (z == 2) ? TOKD : DIM;
    int k0 = blockIdx.y * 32, n0 = blockIdx.x * 32;
    if (n0 >= ncols) return;
    t[threadIdx.y][threadIdx.x] = src[(size_t)(k0 + threadIdx.y) * ncols + n0 + threadIdx.x];
    __syncthreads();
    dst[(size_t)(n0 + threadIdx.y) * DIM + k0 + threadIdx.x] =
        __uint_as_float(f2tf32(t[threadIdx.x][threadIdx.y]));
}

// ---------------------------------------------------------------------------
// ldmatrix-based tile compute: 4 warps (2x2), warp tile 64x64, BK=32,
// smem rows padded to 36 floats
// ---------------------------------------------------------------------------
__device__ __forceinline__ void tile_compute_ldsm(uint32_t sAb, uint32_t sBb,
                                                  float acc[4][8][4],
                                                  int lane, int warpM, int warpN) {
    const int j = lane >> 3, i = lane & 7;
    const int arow = warpM * 64 + (j & 1) * 8 + i;
    const int acol = (j >> 1) * 4;
    const int brow = warpN * 64 + ((j >> 1) & 1) * 8 + i;
    const int bcol = (j & 1) * 4;
    #pragma unroll
    for (int ks = 0; ks < 4; ks++) {
        uint32_t af[4][4], bf[4][4];
        #pragma unroll
        for (int mt = 0; mt < 4; mt++)
            ldsm4(af[mt], sAb + ((arow + mt * 16) * 36 + ks * 8 + acol) * 4);
        #pragma unroll
        for (int ntp = 0; ntp < 4; ntp++)
            ldsm4(bf[ntp], sBb + ((brow + ntp * 16) * 36 + ks * 8 + bcol) * 4);
        #pragma unroll
        for (int mt = 0; mt < 4; mt++)
            #pragma unroll
            for (int nt = 0; nt < 8; nt++)
                mma8(acc[mt][nt], af[mt], &bf[nt >> 1][(nt & 1) * 2]);
    }
}

// ---------------------------------------------------------------------------
// Fused q+k GEMM: 3-stage cp.async pipeline, single sync per iteration.
// grid (8, 256): x<4 -> q n-tile, else k n-tile. 128 threads.
// ---------------------------------------------------------------------------
#define QK_SMF  4608                    // 128*36 floats per tile buffer
#define QK_SMEM (6 * QK_SMF * 4)        // 110592 bytes (3 stages x A,B)

__global__ void __launch_bounds__(128, 2)
mma_gemm_qk2(const float* __restrict__ X,
             const float* __restrict__ bq, const float* __restrict__ bk,
             const float* __restrict__ w_alpha) {
    extern __shared__ float sm[];
    __shared__ float sbias[DIM];
    __shared__ float swa[DIM];

    const int isq = (blockIdx.x < 4);
    const int n0 = (blockIdx.x & 3) * 128;
    const int m0 = blockIdx.y * 128;
    const float* __restrict__ WT   = isq ? g_WqT : g_WkT;
    const float* __restrict__ bias = isq ? bq : bk;
    float* __restrict__ C   = isq ? g_qbuf : g_kbuf;
    float* __restrict__ ssq = isq ? g_ssq_q : g_ssq_k;

    const int tid = threadIdx.x, lane = tid & 31, wid = tid >> 5;
    const int warpM = wid >> 1, warpN = wid & 1;
    uint32_t sA[3], sB[3];
    #pragma unroll
    for (int s = 0; s < 3; s++) {
        sA[s] = smem_u32(sm + (2 * s) * QK_SMF);
        sB[s] = smem_u32(sm + (2 * s + 1) * QK_SMF);
    }

    for (int i = tid; i < DIM; i += 128) { sbias[i] = bias[i]; swa[i] = w_alpha[i]; }

    float acc[4][8][4];
    #pragma unroll
    for (int a = 0; a < 4; a++)
        #pragma unroll
        for (int b = 0; b < 8; b++)
            #pragma unroll
            for (int c = 0; c < 4; c++) acc[a][b][c] = 0.f;

    auto load_tile = [&](int c, int stg) {
        const int k0 = c * 32;
        #pragma unroll
        for (int l = 0; l < 8; l++) {
            int e = tid + l * 128, r = e >> 3, s = e & 7;
            cp16(sA[stg] + (r * 36 + s * 4) * 4, X + (size_t)(m0 + r) * DIM + k0 + s * 4);
        }
        #pragma unroll
        for (int l = 0; l < 8; l++) {
            int e = tid + l * 128, r = e >> 3, s = e & 7;
            cp16(sB[stg] + (r * 36 + s * 4) * 4, WT + (size_t)(n0 + r) * DIM + k0 + s * 4);
        }
        cp_commit();
    };

    load_tile(0, 0);
    load_tile(1, 1);
    #pragma unroll 1
    for (int c = 0; c < 16; c++) {
        if (c + 2 < 16) cp_wait1(); else cp_wait0();
        __syncthreads();                 // stage c visible to all; stage (c+2)%3 free (computed at c-1)
        if (c + 2 < 16) load_tile(c + 2, (c + 2) % 3);
        tile_compute_ldsm(sA[c % 3], sB[c % 3], acc, lane, warpM, warpN);
    }

    const int g = lane >> 2, tg = lane & 3;
    #pragma unroll
    for (int mt = 0; mt < 4; mt++) {
        const int r1 = m0 + warpM * 64 + mt * 16 + g;
        const int r2 = r1 + 8;
        float s1 = 0.f, s2 = 0.f, a1 = 0.f, a2 = 0.f;
        #pragma unroll
        for (int nt = 0; nt < 8; nt++) {
            const int col = n0 + warpN * 64 + nt * 8 + 2 * tg;
            float v0 = acc[mt][nt][0] + sbias[col];
            float v1 = acc[mt][nt][1] + sbias[col + 1];
            float v2 = acc[mt][nt][2] + sbias[col];
            float v3 = acc[mt][nt][3] + sbias[col + 1];
            *(float2*)(C + (size_t)r1 * DIM + col) = make_float2(v0, v1);
            *(float2*)(C + (size_t)r2 * DIM + col) = make_float2(v2, v3);
            s1 = fmaf(v0, v0, fmaf(v1, v1, s1));
            s2 = fmaf(v2, v2, fmaf(v3, v3, s2));
            if (isq) {
                a1 = fmaf(v0, swa[col], fmaf(v1, swa[col + 1], a1));
                a2 = fmaf(v2, swa[col], fmaf(v3, swa[col + 1], a2));
            }
        }
        s1 += __shfl_xor_sync(0xffffffffu, s1, 1); s1 += __shfl_xor_sync(0xffffffffu, s1, 2);
        s2 += __shfl_xor_sync(0xffffffffu, s2, 1); s2 += __shfl_xor_sync(0xffffffffu, s2, 2);
        if (isq) {
            a1 += __shfl_xor_sync(0xffffffffu, a1, 1); a1 += __shfl_xor_sync(0xffffffffu, a1, 2);
            a2 += __shfl_xor_sync(0xffffffffu, a2, 1); a2 += __shfl_xor_sync(0xffffffffu, a2, 2);
        }
        if (tg == 0) {
            atomicAdd(&ssq[r1], s1);
            atomicAdd(&ssq[r2], s2);
            if (isq) { atomicAdd(&g_adot[r1], a1); atomicAdd(&g_adot[r2], a2); }
        }
    }
}

// ---------------------------------------------------------------------------
// Fused finalize_tok + colsum0. 64-row chunks, 8-way ILP.
// grid (64, 8), 512 threads.
// ---------------------------------------------------------------------------
__global__ __launch_bounds__(512) void colsum0_fused() {
    __shared__ float sw[64];
    const int b = blockIdx.y, chunk = blockIdx.x;
    const int t0 = b * NSEQ + chunk * 64;
    const int tid = threadIdx.x;

    if (tid < 64) {
        const int t = t0 + tid;
        float qi = 1.f / fmaxf(sqrtf(g_ssq_q[t]), 1e-12f);
        float ki = 1.f / fmaxf(sqrtf(g_ssq_k[t]), 1e-12f);
        g_qinv[t] = qi;
        g_kinv[t] = ki;
        float a = g_adot[t] * qi * SCALEF;
        sw[tid] = a * qi;
        float av = a * a;
        #pragma unroll
        for (int o = 16; o > 0; o >>= 1) av += __shfl_xor_sync(0xffffffffu, av, o);
        if ((tid & 31) == 0) atomicAdd(&g_asumsq[b], av);
    }
    __syncthreads();

    const int d = tid;
    const float* Mb = g_qbuf + (size_t)t0 * DIM + d;
    float s[8];
    #pragma unroll
    for (int u = 0; u < 8; u++) s[u] = 0.f;
    #pragma unroll
    for (int n = 0; n < 64; n += 8) {
        #pragma unroll
        for (int u = 0; u < 8; u++)
            s[u] = fmaf(sw[n + u], Mb[(size_t)(n + u) * DIM], s[u]);
    }
    float tot = ((s[0] + s[1]) + (s[2] + s[3])) + ((s[4] + s[5]) + (s[6] + s[7]));
    atomicAdd(&g_gqraw[b * DIM + d], tot);
}

// ---------------------------------------------------------------------------
// Fused gq-softmax + beta + colsum1. Each block recomputes gq/gw from
// g_gqraw (block-local smem), then beta per row, then 8-way-ILP colsum.
// grid (64, 8), 512 threads.
// ---------------------------------------------------------------------------
__global__ __launch_bounds__(512) void beta_colsum1_fused(const float* __restrict__ w_beta) {
    __shared__ float sgw[DIM];
    __shared__ float sw[64];
    __shared__ float red[32];
    const int b = blockIdx.y, chunk = blockIdx.x;
    const int t0 = b * NSEQ + chunk * 64;
    const int tid = threadIdx.x, lane = tid & 31, wid = tid >> 5;

    // gq softmax (block-local): gq = softmax(gqraw * ainv); gw = gq * w_beta
    {
        float ainv = 1.f / fmaxf(sqrtf(g_asumsq[b]), 1e-12f);
        float v = g_gqraw[b * DIM + tid] * ainv;
        float mx = block_max(v, red);
        float e = expf(v - mx);
        float s = block_sum(e, red);
        sgw[tid] = (e / s) * w_beta[tid];
    }
    __syncthreads();

    // beta for rows wid*4 .. wid*4+3 (row-interleaved for MLP)
    {
        const int row0 = wid * 4;
        float d0 = 0.f, d1 = 0.f, d2 = 0.f, d3 = 0.f;
        const float* k0p = g_kbuf + (size_t)(t0 + row0 + 0) * DIM;
        const float* k1p = g_kbuf + (size_t)(t0 + row0 + 1) * DIM;
        const float* k2p = g_kbuf + (size_t)(t0 + row0 + 2) * DIM;
        const float* k3p = g_kbuf + (size_t)(t0 + row0 + 3) * DIM;
        #pragma unroll
        for (int jj = 0; jj < 16; jj++) {
            const int idx = lane + 32 * jj;
            const float w = sgw[idx];
            d0 = fmaf(k0p[idx], w, d0);
            d1 = fmaf(k1p[idx], w, d1);
            d2 = fmaf(k2p[idx], w, d2);
            d3 = fmaf(k3p[idx], w, d3);
        }
        #pragma unroll
        for (int o = 16; o > 0; o >>= 1) {
            d0 += __shfl_xor_sync(0xffffffffu, d0, o);
            d1 += __shfl_xor_sync(0xffffffffu, d1, o);
            d2 += __shfl_xor_sync(0xffffffffu, d2, o);
            d3 += __shfl_xor_sync(0xffffffffu, d3, o);
        }
        if (lane == 0) {
            float bsum = 0.f;
            float dv[4] = { d0, d1, d2, d3 };
            #pragma unroll
            for (int r = 0; r < 4; r++) {
                float ki = g_kinv[t0 + row0 + r];
                float bb = dv[r] * SCALEF * ki;
                sw[row0 + r] = bb * ki;
                bsum = fmaf(bb, bb, bsum);
            }
            atomicAdd(&g_bsumsq[b], bsum);
        }
    }
    __syncthreads();

    const int d = tid;
    const float* Mb = g_kbuf + (size_t)t0 * DIM + d;
    float s[8];
    #pragma unroll
    for (int u = 0; u < 8; u++) s[u] = 0.f;
    #pragma unroll
    for (int n = 0; n < 64; n += 8) {
        #pragma unroll
        for (int u = 0; u < 8; u++)
            s[u] = fmaf(sw[n + u], Mb[(size_t)(n + u) * DIM], s[u]);
    }
    float tot = ((s[0] + s[1]) + (s[2] + s[3])) + ((s[4] + s[5]) + (s[6] + s[7]));
    atomicAdd(&g_gkraw[b * DIM + d], tot);
}

// ---------------------------------------------------------------------------
// Final GEMM: out = (gk.*kinv.*kraw + qinv.*qraw)@Wr + br
// Prologue recomputes gq & gk softmaxes block-locally (fused gk_finalize).
// 128 threads, 4 warps 2x2 at 64x64, grid (2, 256). 2-stage A-fusion pipeline.
// ---------------------------------------------------------------------------
#define FIN_SMEM (4 * QK_SMF * 4)   // 73728: A0,B0,A1,B1

__global__ void __launch_bounds__(128, 2)
mma_gemm_final(const float* __restrict__ bias, float* __restrict__ out) {
    extern __shared__ float sm[];
    __shared__ float sbias[TOKD];
    __shared__ float sgq[DIM];
    __shared__ float sgk[DIM];
    __shared__ float sqinv[128];
    __shared__ float skinv[128];
    __shared__ float red[32];

    const int tid = threadIdx.x, lane = tid & 31, wid = tid >> 5;
    const int warpM = wid >> 1, warpN = wid & 1;
    const int m0 = blockIdx.y * 128, n0 = blockIdx.x * 128;
    const int b0 = m0 >> 12;
    const uint32_t sA[2] = { smem_u32(sm),          smem_u32(sm + 2 * QK_SMF) };
    const uint32_t sB[2] = { smem_u32(sm + QK_SMF), smem_u32(sm + 3 * QK_SMF) };

    for (int i = tid; i < TOKD; i += 128) sbias[i] = bias[i];
    { sqinv[tid] = g_qinv[m0 + tid]; skinv[tid] = g_kinv[m0 + tid]; }

    // gq = softmax(gqraw*ainv); gk = softmax(gq*gkraw*binv)  (block-local)
    {
        float ainv = 1.f / fmaxf(sqrtf(g_asumsq[b0]), 1e-12f);
        float binv = 1.f / fmaxf(sqrtf(g_bsumsq[b0]), 1e-12f);
        float v[4];
        #pragma unroll
        for (int j = 0; j < 4; j++) v[j] = g_gqraw[b0 * DIM + tid + j * 128] * ainv;
        float lm = fmaxf(fmaxf(v[0], v[1]), fmaxf(v[2], v[3]));
        float m = block_max(lm, red);
        float e[4], ls = 0.f;
        #pragma unroll
        for (int j = 0; j < 4; j++) { e[j] = expf(v[j] - m); ls += e[j]; }
        float s = block_sum(ls, red);
        #pragma unroll
        for (int j = 0; j < 4; j++) sgq[tid + j * 128] = e[j] / s;
        #pragma unroll
        for (int j = 0; j < 4; j++)
            v[j] = sgq[tid + j * 128] * g_gkraw[b0 * DIM + tid + j * 128] * binv;
        lm = fmaxf(fmaxf(v[0], v[1]), fmaxf(v[2], v[3]));
        m = block_max(lm, red);
        ls = 0.f;
        #pragma unroll
        for (int j = 0; j < 4; j++) { e[j] = expf(v[j] - m); ls += e[j]; }
        s = block_sum(ls, red);
        #pragma unroll
        for (int j = 0; j < 4; j++) sgk[tid + j * 128] = e[j] / s;
    }

    float acc[4][8][4];
    #pragma unroll
    for (int a = 0; a < 4; a++)
        #pragma unroll
        for (int b = 0; b < 8; b++)
            #pragma unroll
            for (int c = 0; c < 4; c++) acc[a][b][c] = 0.f;

    auto load_B = [&](int c, int buf) {
        const int k0 = c * 32;
        #pragma unroll
        for (int l = 0; l < 8; l++) {
            int e = tid + l * 128, r = e >> 3, s = e & 7;
            cp16(sB[buf] + (r * 36 + s * 4) * 4, g_WrT + (size_t)(n0 + r) * DIM + k0 + s * 4);
        }
        cp_commit();
    };

    float4 kv[8], qv[8];
    auto fetch_A = [&](int c) {
        const int k0 = c * 32;
        #pragma unroll
        for (int l = 0; l < 8; l++) {
            int e = tid + l * 128, r = e >> 3, s = e & 7;
            kv[l] = *(const float4*)(g_kbuf + (size_t)(m0 + r) * DIM + k0 + s * 4);
            qv[l] = *(const float4*)(g_qbuf + (size_t)(m0 + r) * DIM + k0 + s * 4);
        }
    };
    auto sts_A = [&](int c, int buf) {
        const int k0 = c * 32;
        #pragma unroll
        for (int l = 0; l < 8; l++) {
            int e = tid + l * 128, r = e >> 3, s = e & 7;
            float qi = sqinv[r], ksc = skinv[r];
            int k = k0 + s * 4;
            float v0 = fmaf(sgk[k + 0] * ksc, kv[l].x, qi * qv[l].x);
            float v1 = fmaf(sgk[k + 1] * ksc, kv[l].y, qi * qv[l].y);
            float v2 = fmaf(sgk[k + 2] * ksc, kv[l].z, qi * qv[l].z);
            float v3 = fmaf(sgk[k + 3] * ksc, kv[l].w, qi * qv[l].w);
            sts128(sA[buf] + (r * 36 + s * 4) * 4,
                   f2tf32(v0), f2tf32(v1), f2tf32(v2), f2tf32(v3));
        }
    };

    fetch_A(0);
    load_B(0, 0);
    __syncthreads();                 // sgq/sgk/sqinv ready before first sts_A
    #pragma unroll 1
    for (int c = 0; c < 16; c++) {
        sts_A(c, c & 1);
        if (c + 1 < 16) { fetch_A(c + 1); load_B(c + 1, (c + 1) & 1); cp_wait1(); }
        else cp_wait0();
        __syncthreads();
        tile_compute_ldsm(sA[c & 1], sB[c & 1], acc, lane, warpM, warpN);
        __syncthreads();
    }

    const int g = lane >> 2, tg = lane & 3;
    #pragma unroll
    for (int mt = 0; mt < 4; mt++) {
        const int r1 = m0 + warpM * 64 + mt * 16 + g;
        const int r2 = r1 + 8;
        #pragma unroll
        for (int nt = 0; nt < 8; nt++) {
            const int col = n0 + warpN * 64 + nt * 8 + 2 * tg;
            float2 o1, o2;
            o1.x = acc[mt][nt][0] + sbias[col];
            o1.y = acc[mt][nt][1] + sbias[col + 1];
            o2.x = acc[mt][nt][2] + sbias[col];
            o2.y = acc[mt][nt][3] + sbias[col + 1];
            *(float2*)(out + (size_t)r1 * TOKD + col) = o1;
            *(float2*)(out + (size_t)r2 * TOKD + col) = o2;
        }
    }
}

// ---------------------------------------------------------------------------
// Launch
// ---------------------------------------------------------------------------
extern "C" void kernel_launch(void* const* d_in, const int* in_sizes, int n_in,
                              void* d_out, int out_size) {
    const float* x  = (const float*)d_in[0];
    const float* Wq = (const float*)d_in[1];
    const float* bq = (const float*)d_in[2];
    const float* Wk = (const float*)d_in[3];
    const float* bk = (const float*)d_in[4];
    const float* Wr = (const float*)d_in[5];
    const float* br = (const float*)d_in[6];
    const float* wa = (const float*)d_in[7];
    const float* wb = (const float*)d_in[8];
    float* out = (float*)d_out;

    cudaFuncSetAttribute(mma_gemm_qk2,   cudaFuncAttributeMaxDynamicSharedMemorySize, QK_SMEM);
    cudaFuncSetAttribute(mma_gemm_final, cudaFuncAttributeMaxDynamicSharedMemorySize, FIN_SMEM);

    transpose_w<<<dim3(16, 16, 3), dim3(32, 32)>>>(Wq, Wk, Wr);
    mma_gemm_qk2<<<dim3(8, 256), 128, QK_SMEM>>>(x, bq, bk, wa);
    colsum0_fused<<<dim3(64, BATCH), 512>>>();
    beta_colsum1_fused<<<dim3(64, BATCH), 512>>>(wb);
    mma_gemm_final<<<dim3(2, 256), 128, FIN_SMEM>>>(br, out);
}